// round 6
// baseline (speedup 1.0000x reference)
#include <cuda_runtime.h>
#include <math.h>

// Problem constants (fixed by the reference)
#define NN 100000   // nodes
#define EE 1600000  // edges
#define HH 128      // channels
#define GG 64       // graphs

// ---------------- static device scratch (no allocations allowed) ----------
__device__ __align__(16) float g_t [(size_t)NN * HH];   // h @ W
__device__ __align__(16) float g_hA[(size_t)NN * HH];   // ping
__device__ __align__(16) float g_hB[(size_t)NN * HH];   // pong
__device__ float g_dinv[NN];              // deg -> d^{-1/2} (in place)
__device__ float g_norm[EE];
__device__ int   g_row[EE];
__device__ int   g_col[EE];
__device__ __align__(16) float g_gsum[GG * HH];
__device__ float g_gcnt[GG];
__device__ int   g_ei_is64;               // dtype flags (auto-detected)
__device__ int   g_b_is64;

__device__ __forceinline__ float* SEL(int s) {
    return (s == 0) ? g_t : (s == 1) ? g_hA : g_hB;
}

// ---------------- dtype detection ------------------------------------------
// For int64 payloads with values < 2^31, every odd 32-bit word is zero.
// For int32 payloads the sampled words are (essentially surely) not all zero.
// All sampled indices stay within the int32-interpretation buffer extent,
// so the reads are in-bounds under either true dtype.
__global__ void detect_k(const int* __restrict__ ei32,
                         const int* __restrict__ b32)
{
    int tid = threadIdx.x;                       // 256 threads, 1 block
    // edge_index: odd indices spread over [1, 2*EE)
    int je = 1 + 12500 * tid;                    // max 3,187,501 < 3,200,000
    int ei_nz = (ei32[je] != 0);
    // batch (sorted): odd indices in upper half [50001, 99471]
    int jb = 50001 + 194 * tid;
    int b_nz = (b32[jb] != 0);
    int any_ei = __syncthreads_or(ei_nz);
    int any_b  = __syncthreads_or(b_nz);
    if (tid == 0) {
        g_ei_is64 = (any_ei == 0);
        g_b_is64  = (any_b  == 0);
    }
}

// ---------------- small utility kernels -----------------------------------
__global__ void init_k() {
    int i = blockIdx.x * blockDim.x + threadIdx.x;
    if (i < NN) g_dinv[i] = 1.0f;           // self-loop weight seeds degree
    if (i < GG * HH) g_gsum[i] = 0.0f;
    if (i < GG) g_gcnt[i] = 0.0f;
}

__global__ void prep_k(const void* __restrict__ ei,
                       const float* __restrict__ ew) {
    int e = blockIdx.x * blockDim.x + threadIdx.x;
    if (e >= EE) return;
    int r, c;
    if (g_ei_is64) {
        const long long* p = (const long long*)ei;
        r = (int)p[e]; c = (int)p[EE + e];
    } else {
        const int* p = (const int*)ei;
        r = p[e]; c = p[EE + e];
    }
    g_row[e] = r;
    g_col[e] = c;
    atomicAdd(&g_dinv[c], ew[e]);           // weighted in-degree
}

__global__ void dinv_k() {
    int i = blockIdx.x * blockDim.x + threadIdx.x;
    if (i >= NN) return;
    float d = g_dinv[i];
    g_dinv[i] = (d > 0.0f) ? rsqrtf(d) : 0.0f;
}

__global__ void norm_k(const float* __restrict__ ew) {
    int e = blockIdx.x * blockDim.x + threadIdx.x;
    if (e >= EE) return;
    g_norm[e] = g_dinv[g_row[e]] * ew[e] * g_dinv[g_col[e]];
}

// ---------------- SGEMM: g_t = act(A)[N,128] @ W[128,128] ------------------
// 128x128 block tile, 256 threads, 8x8 per-thread register tile.
__global__ void __launch_bounds__(256)
gemm_k(const float* __restrict__ Aext, int selA,
       const float* __restrict__ W, int relu_in)
{
    __shared__ __align__(16) float As[128][17];
    __shared__ __align__(16) float Ws[16][132];

    const float* A = (selA < 0) ? Aext : SEL(selA);
    float* C = g_t;

    const int tid  = threadIdx.x;
    const int tm   = tid >> 4;         // 0..15
    const int tn   = tid & 15;         // 0..15
    const int row0 = blockIdx.x * 128;

    float acc[8][8];
#pragma unroll
    for (int i = 0; i < 8; ++i)
#pragma unroll
        for (int j = 0; j < 8; ++j) acc[i][j] = 0.0f;

    const int ar = tid >> 1;           // 0..127
    const int ac = (tid & 1) * 8;      // 0 or 8
    const int wr = tid >> 4;           // 0..15
    const int wc = (tid & 15) * 8;     // 0..120

    for (int k0 = 0; k0 < 128; k0 += 16) {
        float av[8];
        if (row0 + ar < NN) {
            const float4* p =
                (const float4*)(A + (size_t)(row0 + ar) * 128 + k0 + ac);
            float4 u0 = p[0], u1 = p[1];
            av[0] = u0.x; av[1] = u0.y; av[2] = u0.z; av[3] = u0.w;
            av[4] = u1.x; av[5] = u1.y; av[6] = u1.z; av[7] = u1.w;
            if (relu_in) {
#pragma unroll
                for (int j = 0; j < 8; ++j) av[j] = fmaxf(av[j], 0.0f);
            }
        } else {
#pragma unroll
            for (int j = 0; j < 8; ++j) av[j] = 0.0f;
        }
#pragma unroll
        for (int j = 0; j < 8; ++j) As[ar][ac + j] = av[j];

        const float4* wp = (const float4*)(W + (size_t)(k0 + wr) * 128 + wc);
        float4 w0 = wp[0], w1 = wp[1];
        *(float4*)&Ws[wr][wc]     = w0;
        *(float4*)&Ws[wr][wc + 4] = w1;
        __syncthreads();

#pragma unroll
        for (int kk = 0; kk < 16; ++kk) {
            float a[8], b[8];
#pragma unroll
            for (int i = 0; i < 8; ++i) a[i] = As[tm * 8 + i][kk];
            float4 b0 = *(const float4*)&Ws[kk][tn * 8];
            float4 b1 = *(const float4*)&Ws[kk][tn * 8 + 4];
            b[0] = b0.x; b[1] = b0.y; b[2] = b0.z; b[3] = b0.w;
            b[4] = b1.x; b[5] = b1.y; b[6] = b1.z; b[7] = b1.w;
#pragma unroll
            for (int i = 0; i < 8; ++i)
#pragma unroll
                for (int j = 0; j < 8; ++j)
                    acc[i][j] = fmaf(a[i], b[j], acc[i][j]);
        }
        __syncthreads();
    }

#pragma unroll
    for (int i = 0; i < 8; ++i) {
        int m = row0 + tm * 8 + i;
        if (m < NN) {
            float4 o0 = make_float4(acc[i][0], acc[i][1], acc[i][2], acc[i][3]);
            float4 o1 = make_float4(acc[i][4], acc[i][5], acc[i][6], acc[i][7]);
            float4* cp = (float4*)(C + (size_t)m * 128 + tn * 8);
            cp[0] = o0;
            cp[1] = o1;
        }
    }
}

// ---------------- out[i] = b + t[i] * dinv[i]^2  (self-loop + bias) --------
__global__ void selfbias_k(const float* __restrict__ b, int selOut)
{
    int idx = blockIdx.x * blockDim.x + threadIdx.x;   // over N*H/4 float4s
    if (idx >= NN * HH / 4) return;
    float* out = SEL(selOut);
    int node = idx >> 5;          // 32 float4 per node
    int q    = idx & 31;
    float d = g_dinv[node];
    float s = d * d;
    float4 tv = ((const float4*)g_t)[idx];
    float4 bb = ((const float4*)b)[q];
    float4 o;
    o.x = fmaf(tv.x, s, bb.x);
    o.y = fmaf(tv.y, s, bb.y);
    o.z = fmaf(tv.z, s, bb.z);
    o.w = fmaf(tv.w, s, bb.w);
    ((float4*)out)[idx] = o;
}

// ---------------- edge scatter: out[col] += norm * t[row] ------------------
// one warp per edge; each lane handles 4 consecutive channels (scalar REDs).
__global__ void scatter_k(int selOut)
{
    int gt = blockIdx.x * blockDim.x + threadIdx.x;
    int e = gt >> 5;
    if (e >= EE) return;
    float* out = SEL(selOut);
    int lane = threadIdx.x & 31;
    int r = g_row[e];
    int c = g_col[e];
    float w = g_norm[e];
    float4 v = ((const float4*)(g_t + (size_t)r * HH))[lane];
    float* dst = out + (size_t)c * HH + lane * 4;
    atomicAdd(dst + 0, v.x * w);
    atomicAdd(dst + 1, v.y * w);
    atomicAdd(dst + 2, v.z * w);
    atomicAdd(dst + 3, v.w * w);
}

// ---------------- pooling: per-graph sum of relu(h), plus counts -----------
__global__ void pool_k(const void* __restrict__ batch)
{
    int gt = blockIdx.x * blockDim.x + threadIdx.x;
    int i = gt >> 5;
    if (i >= NN) return;
    int lane = threadIdx.x & 31;
    int g = g_b_is64 ? (int)((const long long*)batch)[i]
                     : ((const int*)batch)[i];
    float4 v = ((const float4*)(g_hA + (size_t)i * HH))[lane];
    float* dst = &g_gsum[g * HH + lane * 4];
    atomicAdd(dst + 0, fmaxf(v.x, 0.0f));
    atomicAdd(dst + 1, fmaxf(v.y, 0.0f));
    atomicAdd(dst + 2, fmaxf(v.z, 0.0f));
    atomicAdd(dst + 3, fmaxf(v.w, 0.0f));
    if (lane == 0) atomicAdd(&g_gcnt[g], 1.0f);
}

// ---------------- final: out[g] = (gsum[g]/max(cnt,1)) . lin_w + lin_b -----
__global__ void final_k(const float* __restrict__ lw,
                        const float* __restrict__ lb,
                        float* __restrict__ out)
{
    int g = blockIdx.x;       // 64 blocks
    int t = threadIdx.x;      // 128 threads
    float inv = 1.0f / fmaxf(g_gcnt[g], 1.0f);
    float v = g_gsum[g * HH + t] * inv * lw[t];
#pragma unroll
    for (int o = 16; o > 0; o >>= 1)
        v += __shfl_down_sync(0xffffffffu, v, o);
    __shared__ float sm[4];
    if ((t & 31) == 0) sm[t >> 5] = v;
    __syncthreads();
    if (t == 0) out[g] = sm[0] + sm[1] + sm[2] + sm[3] + lb[0];
}

// ---------------- launcher --------------------------------------------------
extern "C" void kernel_launch(void* const* d_in, const int* in_sizes, int n_in,
                              void* d_out, int out_size)
{
    // Locate inputs by element count (robust to metadata ordering).
    const float* x = nullptr;
    const float* ew = nullptr;
    const void*  ei = nullptr;     // int32 or int64 (auto-detected on device)
    const void*  batch = nullptr;  // int32 or int64
    const float* Wm[3] = {nullptr, nullptr, nullptr};
    const float* v128[4] = {nullptr, nullptr, nullptr, nullptr}; // b1,b2,b3,lin_w
    const float* linb = nullptr;
    int wi = 0, bi = 0;
    for (int i = 0; i < n_in; ++i) {
        int s = in_sizes[i];
        if      (s == NN * HH)  x = (const float*)d_in[i];
        else if (s == EE)       ew = (const float*)d_in[i];
        else if (s == 2 * EE)   ei = d_in[i];
        else if (s == NN)       batch = d_in[i];
        else if (s == HH * HH)  { if (wi < 3) Wm[wi++] = (const float*)d_in[i]; }
        else if (s == HH)       { if (bi < 4) v128[bi++] = (const float*)d_in[i]; }
        else if (s == 1)        linb = (const float*)d_in[i];
    }
    const float* lw = v128[3];
    float* out = (float*)d_out;

    const int TB = 256;
    const int gN  = (NN + TB - 1) / TB;
    const int gE  = (EE + TB - 1) / TB;
    const int gNH = (NN * HH / 4 + TB - 1) / TB;
    const int gSc = (int)(((long long)EE * 32 + TB - 1) / TB);  // warp/edge
    const int gPl = (int)(((long long)NN * 32 + TB - 1) / TB);  // warp/node
    const int gGm = (NN + 127) / 128;

    // dtype detection + degree / normalization precompute
    detect_k<<<1, 256>>>((const int*)ei, (const int*)batch);
    init_k<<<gN, TB>>>();
    prep_k<<<gE, TB>>>(ei, ew);
    dinv_k<<<gN, TB>>>();
    norm_k<<<gE, TB>>>(ew);

    // Layer 1: t = x @ W1 ; hA = b1 + dinv^2*t ; hA += scatter(t)
    gemm_k<<<gGm, TB>>>(x, -1, Wm[0], 0);
    selfbias_k<<<gNH, TB>>>(v128[0], 1);
    scatter_k<<<gSc, TB>>>(1);

    // Layer 2 (input relu fused into GEMM load): reads hA, writes hB
    gemm_k<<<gGm, TB>>>(nullptr, 1, Wm[1], 1);
    selfbias_k<<<gNH, TB>>>(v128[1], 2);
    scatter_k<<<gSc, TB>>>(2);

    // Layer 3: reads hB, writes hA
    gemm_k<<<gGm, TB>>>(nullptr, 2, Wm[2], 1);
    selfbias_k<<<gNH, TB>>>(v128[2], 1);
    scatter_k<<<gSc, TB>>>(1);

    // Pool (relu fused) + final linear
    pool_k<<<gPl, TB>>>(batch);
    final_k<<<GG, HH>>>(lw, linb, out);
}

// round 7
// speedup vs baseline: 2.0937x; 2.0937x over previous
#include <cuda_runtime.h>
#include <math.h>

// Problem constants (fixed by the reference)
#define NN 100000   // nodes
#define EE 1600000  // edges
#define HH 128      // channels
#define GG 64       // graphs

// ---------------- static device scratch (no allocations allowed) ----------
__device__ __align__(16) float g_t [(size_t)NN * HH];   // h @ W
__device__ __align__(16) float g_hA[(size_t)NN * HH];   // ping
__device__ __align__(16) float g_hB[(size_t)NN * HH];   // pong
__device__ float g_dinv[NN];              // deg -> d^{-1/2} (in place)
__device__ int   g_row[EE];
__device__ int   g_col[EE];
// CSR (destination-sorted) adjacency, built once
__device__ int   g_cnt[NN];               // int in-degree
__device__ int   g_off[NN + 1];           // exclusive scan of cnt
__device__ int   g_fill[NN];              // slot fill counters
__device__ int   g_bsum[256];             // block sums for scan
__device__ int   g_src[EE];               // source node, sorted by dst
__device__ float g_w  [EE];               // norm weight, sorted by dst
__device__ __align__(16) float g_gsum[GG * HH];
__device__ float g_gcnt[GG];
__device__ int   g_ei_is64;               // dtype flags (auto-detected)
__device__ int   g_b_is64;

__device__ __forceinline__ float* SEL(int s) {
    return (s == 0) ? g_t : (s == 1) ? g_hA : g_hB;
}

// ---------------- dtype detection ------------------------------------------
// int64 payloads with values < 2^31 have all odd 32-bit words zero; int32
// payloads (random edge targets / sorted batch ids in the upper half)
// essentially never do. All sampled offsets are in-bounds under either dtype.
__global__ void detect_k(const int* __restrict__ ei32,
                         const int* __restrict__ b32)
{
    int tid = threadIdx.x;                       // 256 threads, 1 block
    int je = 1 + 12500 * tid;                    // odd words across [1, 2*EE)
    int ei_nz = (ei32[je] != 0);
    int jb = 50001 + 194 * tid;                  // odd words, upper half of N
    int b_nz = (b32[jb] != 0);
    int any_ei = __syncthreads_or(ei_nz);
    int any_b  = __syncthreads_or(b_nz);
    if (tid == 0) {
        g_ei_is64 = (any_ei == 0);
        g_b_is64  = (any_b  == 0);
    }
}

// ---------------- init ------------------------------------------------------
__global__ void init_k() {
    int i = blockIdx.x * blockDim.x + threadIdx.x;
    if (i < NN) { g_dinv[i] = 1.0f; g_cnt[i] = 0; g_fill[i] = 0; }
    if (i < GG * HH) g_gsum[i] = 0.0f;
    if (i < GG) g_gcnt[i] = 0.0f;
}

// ---------------- edge prep: decode indices, weighted degree, int count ----
__global__ void prep_k(const void* __restrict__ ei,
                       const float* __restrict__ ew) {
    int e = blockIdx.x * blockDim.x + threadIdx.x;
    if (e >= EE) return;
    int r, c;
    if (g_ei_is64) {
        const long long* p = (const long long*)ei;
        r = (int)p[e]; c = (int)p[EE + e];
    } else {
        const int* p = (const int*)ei;
        r = p[e]; c = p[EE + e];
    }
    g_row[e] = r;
    g_col[e] = c;
    atomicAdd(&g_dinv[c], ew[e]);           // weighted in-degree
    atomicAdd(&g_cnt[c], 1);                // integer in-degree (for CSR)
}

__global__ void dinv_k() {
    int i = blockIdx.x * blockDim.x + threadIdx.x;
    if (i >= NN) return;
    float d = g_dinv[i];
    g_dinv[i] = (d > 0.0f) ? rsqrtf(d) : 0.0f;
}

// ---------------- 3-kernel exclusive scan of g_cnt -> g_off ----------------
#define SCAN_B 512
__global__ void scan1_k() {      // per-block exclusive scan + block totals
    __shared__ int sm[SCAN_B];
    int t = threadIdx.x;
    int idx = blockIdx.x * SCAN_B + t;
    int v = (idx < NN) ? g_cnt[idx] : 0;
    sm[t] = v;
    __syncthreads();
#pragma unroll
    for (int o = 1; o < SCAN_B; o <<= 1) {
        int x = (t >= o) ? sm[t - o] : 0;
        __syncthreads();
        sm[t] += x;
        __syncthreads();
    }
    if (idx < NN) g_off[idx] = sm[t] - v;        // exclusive
    if (t == SCAN_B - 1) g_bsum[blockIdx.x] = sm[t];
}
__global__ void scan2_k(int nblk) {  // single block: scan block totals
    __shared__ int sm[256];
    int t = threadIdx.x;
    int v = (t < nblk) ? g_bsum[t] : 0;
    sm[t] = v;
    __syncthreads();
#pragma unroll
    for (int o = 1; o < 256; o <<= 1) {
        int x = (t >= o) ? sm[t - o] : 0;
        __syncthreads();
        sm[t] += x;
        __syncthreads();
    }
    if (t < nblk) g_bsum[t] = sm[t] - v;         // exclusive
}
__global__ void scan3_k() {
    int idx = blockIdx.x * SCAN_B + threadIdx.x;
    if (idx < NN) g_off[idx] += g_bsum[blockIdx.x];
    if (idx == 0) g_off[NN] = EE;
}

// ---------------- build sorted adjacency (counting-sort fill) --------------
__global__ void build_k(const float* __restrict__ ew) {
    int e = blockIdx.x * blockDim.x + threadIdx.x;
    if (e >= EE) return;
    int r = g_row[e], c = g_col[e];
    int pos = g_off[c] + atomicAdd(&g_fill[c], 1);
    g_src[pos] = r;
    g_w[pos]   = g_dinv[r] * ew[e] * g_dinv[c];
}

// ---------------- SGEMM: g_t = act(A)[N,128] @ W[128,128] ------------------
// 128x128 block tile, 256 threads, 8x8 per-thread register tile.
__global__ void __launch_bounds__(256)
gemm_k(const float* __restrict__ Aext, int selA,
       const float* __restrict__ W, int relu_in)
{
    __shared__ __align__(16) float As[128][17];
    __shared__ __align__(16) float Ws[16][132];

    const float* A = (selA < 0) ? Aext : SEL(selA);
    float* C = g_t;

    const int tid  = threadIdx.x;
    const int tm   = tid >> 4;         // 0..15
    const int tn   = tid & 15;         // 0..15
    const int row0 = blockIdx.x * 128;

    float acc[8][8];
#pragma unroll
    for (int i = 0; i < 8; ++i)
#pragma unroll
        for (int j = 0; j < 8; ++j) acc[i][j] = 0.0f;

    const int ar = tid >> 1;           // 0..127
    const int ac = (tid & 1) * 8;      // 0 or 8
    const int wr = tid >> 4;           // 0..15
    const int wc = (tid & 15) * 8;     // 0..120

    for (int k0 = 0; k0 < 128; k0 += 16) {
        float av[8];
        if (row0 + ar < NN) {
            const float4* p =
                (const float4*)(A + (size_t)(row0 + ar) * 128 + k0 + ac);
            float4 u0 = p[0], u1 = p[1];
            av[0] = u0.x; av[1] = u0.y; av[2] = u0.z; av[3] = u0.w;
            av[4] = u1.x; av[5] = u1.y; av[6] = u1.z; av[7] = u1.w;
            if (relu_in) {
#pragma unroll
                for (int j = 0; j < 8; ++j) av[j] = fmaxf(av[j], 0.0f);
            }
        } else {
#pragma unroll
            for (int j = 0; j < 8; ++j) av[j] = 0.0f;
        }
#pragma unroll
        for (int j = 0; j < 8; ++j) As[ar][ac + j] = av[j];

        const float4* wp = (const float4*)(W + (size_t)(k0 + wr) * 128 + wc);
        float4 w0 = wp[0], w1 = wp[1];
        *(float4*)&Ws[wr][wc]     = w0;
        *(float4*)&Ws[wr][wc + 4] = w1;
        __syncthreads();

#pragma unroll
        for (int kk = 0; kk < 16; ++kk) {
            float a[8], b[8];
#pragma unroll
            for (int i = 0; i < 8; ++i) a[i] = As[tm * 8 + i][kk];
            float4 b0 = *(const float4*)&Ws[kk][tn * 8];
            float4 b1 = *(const float4*)&Ws[kk][tn * 8 + 4];
            b[0] = b0.x; b[1] = b0.y; b[2] = b0.z; b[3] = b0.w;
            b[4] = b1.x; b[5] = b1.y; b[6] = b1.z; b[7] = b1.w;
#pragma unroll
            for (int i = 0; i < 8; ++i)
#pragma unroll
                for (int j = 0; j < 8; ++j)
                    acc[i][j] = fmaf(a[i], b[j], acc[i][j]);
        }
        __syncthreads();
    }

#pragma unroll
    for (int i = 0; i < 8; ++i) {
        int m = row0 + tm * 8 + i;
        if (m < NN) {
            float4 o0 = make_float4(acc[i][0], acc[i][1], acc[i][2], acc[i][3]);
            float4 o1 = make_float4(acc[i][4], acc[i][5], acc[i][6], acc[i][7]);
            float4* cp = (float4*)(C + (size_t)m * 128 + tn * 8);
            cp[0] = o0;
            cp[1] = o1;
        }
    }
}

// ---------------- fused aggregation (gather, no atomics) -------------------
// out[n] = bias + dinv[n]^2 * t[n] + sum_{e in in(n)} w[e] * t[src[e]]
// One warp per node; lane l owns channels [4l, 4l+4). 4-edge unroll for MLP.
__global__ void __launch_bounds__(256)
agg_k(const float* __restrict__ bias, int selOut)
{
    int warp = (blockIdx.x * blockDim.x + threadIdx.x) >> 5;
    if (warp >= NN) return;
    int lane = threadIdx.x & 31;
    float* out = SEL(selOut);

    float d = g_dinv[warp];
    float s = d * d;
    float4 acc = ((const float4*)bias)[lane];
    float4 tv  = ((const float4*)(g_t + (size_t)warp * HH))[lane];
    acc.x = fmaf(tv.x, s, acc.x);
    acc.y = fmaf(tv.y, s, acc.y);
    acc.z = fmaf(tv.z, s, acc.z);
    acc.w = fmaf(tv.w, s, acc.w);

    int k   = g_off[warp];
    int end = g_off[warp + 1];

    for (; k + 4 <= end; k += 4) {
        int   r0 = g_src[k],   r1 = g_src[k+1],
              r2 = g_src[k+2], r3 = g_src[k+3];
        float w0 = g_w[k],   w1 = g_w[k+1],
              w2 = g_w[k+2], w3 = g_w[k+3];
        float4 v0 = __ldg((const float4*)(g_t + (size_t)r0 * HH) + lane);
        float4 v1 = __ldg((const float4*)(g_t + (size_t)r1 * HH) + lane);
        float4 v2 = __ldg((const float4*)(g_t + (size_t)r2 * HH) + lane);
        float4 v3 = __ldg((const float4*)(g_t + (size_t)r3 * HH) + lane);
        acc.x = fmaf(v0.x, w0, acc.x); acc.y = fmaf(v0.y, w0, acc.y);
        acc.z = fmaf(v0.z, w0, acc.z); acc.w = fmaf(v0.w, w0, acc.w);
        acc.x = fmaf(v1.x, w1, acc.x); acc.y = fmaf(v1.y, w1, acc.y);
        acc.z = fmaf(v1.z, w1, acc.z); acc.w = fmaf(v1.w, w1, acc.w);
        acc.x = fmaf(v2.x, w2, acc.x); acc.y = fmaf(v2.y, w2, acc.y);
        acc.z = fmaf(v2.z, w2, acc.z); acc.w = fmaf(v2.w, w2, acc.w);
        acc.x = fmaf(v3.x, w3, acc.x); acc.y = fmaf(v3.y, w3, acc.y);
        acc.z = fmaf(v3.z, w3, acc.z); acc.w = fmaf(v3.w, w3, acc.w);
    }
    for (; k < end; ++k) {
        int   r = g_src[k];
        float w = g_w[k];
        float4 v = __ldg((const float4*)(g_t + (size_t)r * HH) + lane);
        acc.x = fmaf(v.x, w, acc.x); acc.y = fmaf(v.y, w, acc.y);
        acc.z = fmaf(v.z, w, acc.z); acc.w = fmaf(v.w, w, acc.w);
    }

    ((float4*)(out + (size_t)warp * HH))[lane] = acc;
}

// ---------------- pooling: per-graph sum of relu(h), plus counts -----------
__global__ void pool_k(const void* __restrict__ batch)
{
    int gt = blockIdx.x * blockDim.x + threadIdx.x;
    int i = gt >> 5;
    if (i >= NN) return;
    int lane = threadIdx.x & 31;
    int g = g_b_is64 ? (int)((const long long*)batch)[i]
                     : ((const int*)batch)[i];
    float4 v = ((const float4*)(g_hA + (size_t)i * HH))[lane];
    float* dst = &g_gsum[g * HH + lane * 4];
    atomicAdd(dst + 0, fmaxf(v.x, 0.0f));
    atomicAdd(dst + 1, fmaxf(v.y, 0.0f));
    atomicAdd(dst + 2, fmaxf(v.z, 0.0f));
    atomicAdd(dst + 3, fmaxf(v.w, 0.0f));
    if (lane == 0) atomicAdd(&g_gcnt[g], 1.0f);
}

// ---------------- final: out[g] = (gsum[g]/max(cnt,1)) . lin_w + lin_b -----
__global__ void final_k(const float* __restrict__ lw,
                        const float* __restrict__ lb,
                        float* __restrict__ out)
{
    int g = blockIdx.x;       // 64 blocks
    int t = threadIdx.x;      // 128 threads
    float inv = 1.0f / fmaxf(g_gcnt[g], 1.0f);
    float v = g_gsum[g * HH + t] * inv * lw[t];
#pragma unroll
    for (int o = 16; o > 0; o >>= 1)
        v += __shfl_down_sync(0xffffffffu, v, o);
    __shared__ float sm[4];
    if ((t & 31) == 0) sm[t >> 5] = v;
    __syncthreads();
    if (t == 0) out[g] = sm[0] + sm[1] + sm[2] + sm[3] + lb[0];
}

// ---------------- launcher --------------------------------------------------
extern "C" void kernel_launch(void* const* d_in, const int* in_sizes, int n_in,
                              void* d_out, int out_size)
{
    // Locate inputs by element count (robust to metadata ordering).
    const float* x = nullptr;
    const float* ew = nullptr;
    const void*  ei = nullptr;     // int32 or int64 (auto-detected on device)
    const void*  batch = nullptr;  // int32 or int64
    const float* Wm[3] = {nullptr, nullptr, nullptr};
    const float* v128[4] = {nullptr, nullptr, nullptr, nullptr}; // b1,b2,b3,lin_w
    const float* linb = nullptr;
    int wi = 0, bi = 0;
    for (int i = 0; i < n_in; ++i) {
        int s = in_sizes[i];
        if      (s == NN * HH)  x = (const float*)d_in[i];
        else if (s == EE)       ew = (const float*)d_in[i];
        else if (s == 2 * EE)   ei = d_in[i];
        else if (s == NN)       batch = d_in[i];
        else if (s == HH * HH)  { if (wi < 3) Wm[wi++] = (const float*)d_in[i]; }
        else if (s == HH)       { if (bi < 4) v128[bi++] = (const float*)d_in[i]; }
        else if (s == 1)        linb = (const float*)d_in[i];
    }
    const float* lw = v128[3];
    float* out = (float*)d_out;

    const int TB = 256;
    const int gN  = (NN + TB - 1) / TB;
    const int gE  = (EE + TB - 1) / TB;
    const int gAg = (int)(((long long)NN * 32 + TB - 1) / TB);  // warp/node
    const int gPl = gAg;
    const int gGm = (NN + 127) / 128;
    const int nScanBlk = (NN + SCAN_B - 1) / SCAN_B;            // 196

    // dtype detection, degrees, CSR build (graph is static across layers)
    detect_k<<<1, 256>>>((const int*)ei, (const int*)batch);
    init_k<<<gN, TB>>>();
    prep_k<<<gE, TB>>>(ei, ew);
    dinv_k<<<gN, TB>>>();
    scan1_k<<<nScanBlk, SCAN_B>>>();
    scan2_k<<<1, 256>>>(nScanBlk);
    scan3_k<<<nScanBlk, SCAN_B>>>();
    build_k<<<gE, TB>>>(ew);

    // Layer 1: t = x @ W1 ; hA = b1 + dinv^2*t + gather
    gemm_k<<<gGm, TB>>>(x, -1, Wm[0], 0);
    agg_k<<<gAg, TB>>>(v128[0], 1);

    // Layer 2 (input relu fused into GEMM load): reads hA, writes hB
    gemm_k<<<gGm, TB>>>(nullptr, 1, Wm[1], 1);
    agg_k<<<gAg, TB>>>(v128[1], 2);

    // Layer 3: reads hB, writes hA
    gemm_k<<<gGm, TB>>>(nullptr, 2, Wm[2], 1);
    agg_k<<<gAg, TB>>>(v128[2], 1);

    // Pool (relu fused) + final linear
    pool_k<<<gPl, TB>>>(batch);
    final_k<<<GG, HH>>>(lw, linb, out);
}

// round 8
// speedup vs baseline: 2.6306x; 1.2564x over previous
#include <cuda_runtime.h>
#include <math.h>

// Problem constants (fixed by the reference)
#define NN 100000   // nodes
#define EE 1600000  // edges
#define HH 128      // channels
#define GG 64       // graphs

// ---------------- static device scratch (no allocations allowed) ----------
__device__ __align__(16) float g_t [(size_t)NN * HH];   // h @ W
__device__ __align__(16) float g_h [(size_t)NN * HH];   // layer activations
__device__ float g_dinv[NN];              // deg -> d^{-1/2} (in place)
__device__ int   g_row[EE];
__device__ int   g_col[EE];
// CSR (destination-sorted) adjacency, built once
__device__ int   g_cnt[NN];               // int in-degree
__device__ int   g_off[NN + 1];           // exclusive scan of cnt
__device__ int   g_fill[NN];              // slot fill counters
__device__ int   g_bsum[256];             // block sums for scan
__device__ int   g_src[EE];               // source node, sorted by dst
__device__ float g_w  [EE];               // norm weight, sorted by dst
__device__ int   g_ei_is64;               // dtype flags (auto-detected)
__device__ int   g_b_is64;

// ---------------- f32x2 helpers (Blackwell packed fp32 FMA) ----------------
__device__ __forceinline__ unsigned long long ffma2(
    unsigned long long a, unsigned long long b, unsigned long long c)
{
    unsigned long long d;
    asm("fma.rn.f32x2 %0, %1, %2, %3;" : "=l"(d) : "l"(a), "l"(b), "l"(c));
    return d;
}
__device__ __forceinline__ unsigned long long pack_dup(float a)
{
    unsigned long long r;
    asm("mov.b64 %0, {%1, %1};" : "=l"(r) : "f"(a));
    return r;
}
__device__ __forceinline__ float2 unpack2(unsigned long long v)
{
    float lo, hi;
    asm("mov.b64 {%0, %1}, %2;" : "=f"(lo), "=f"(hi) : "l"(v));
    return make_float2(lo, hi);
}

// ---------------- dtype detection ------------------------------------------
// int64 payloads with values < 2^31 have all odd 32-bit words zero; int32
// payloads (random edge targets / sorted batch ids in the upper half)
// essentially never do. All sampled offsets are in-bounds under either dtype.
__global__ void detect_k(const int* __restrict__ ei32,
                         const int* __restrict__ b32)
{
    int tid = threadIdx.x;                       // 256 threads, 1 block
    int je = 1 + 12500 * tid;                    // odd words across [1, 2*EE)
    int ei_nz = (ei32[je] != 0);
    int jb = 50001 + 194 * tid;                  // odd words, upper half of N
    int b_nz = (b32[jb] != 0);
    int any_ei = __syncthreads_or(ei_nz);
    int any_b  = __syncthreads_or(b_nz);
    if (tid == 0) {
        g_ei_is64 = (any_ei == 0);
        g_b_is64  = (any_b  == 0);
    }
}

// ---------------- init ------------------------------------------------------
__global__ void init_k() {
    int i = blockIdx.x * blockDim.x + threadIdx.x;
    if (i < NN) { g_dinv[i] = 1.0f; g_cnt[i] = 0; g_fill[i] = 0; }
}

// ---------------- edge prep: decode indices, weighted degree, int count ----
__global__ void prep_k(const void* __restrict__ ei,
                       const float* __restrict__ ew) {
    int e = blockIdx.x * blockDim.x + threadIdx.x;
    if (e >= EE) return;
    int r, c;
    if (g_ei_is64) {
        const long long* p = (const long long*)ei;
        r = (int)p[e]; c = (int)p[EE + e];
    } else {
        const int* p = (const int*)ei;
        r = p[e]; c = p[EE + e];
    }
    g_row[e] = r;
    g_col[e] = c;
    atomicAdd(&g_dinv[c], ew[e]);           // weighted in-degree
    atomicAdd(&g_cnt[c], 1);                // integer in-degree (for CSR)
}

__global__ void dinv_k() {
    int i = blockIdx.x * blockDim.x + threadIdx.x;
    if (i >= NN) return;
    float d = g_dinv[i];
    g_dinv[i] = (d > 0.0f) ? rsqrtf(d) : 0.0f;
}

// ---------------- 3-kernel exclusive scan of g_cnt -> g_off ----------------
#define SCAN_B 512
__global__ void scan1_k() {      // per-block exclusive scan + block totals
    __shared__ int sm[SCAN_B];
    int t = threadIdx.x;
    int idx = blockIdx.x * SCAN_B + t;
    int v = (idx < NN) ? g_cnt[idx] : 0;
    sm[t] = v;
    __syncthreads();
#pragma unroll
    for (int o = 1; o < SCAN_B; o <<= 1) {
        int x = (t >= o) ? sm[t - o] : 0;
        __syncthreads();
        sm[t] += x;
        __syncthreads();
    }
    if (idx < NN) g_off[idx] = sm[t] - v;        // exclusive
    if (t == SCAN_B - 1) g_bsum[blockIdx.x] = sm[t];
}
__global__ void scan2_k(int nblk) {  // single block: scan block totals
    __shared__ int sm[256];
    int t = threadIdx.x;
    int v = (t < nblk) ? g_bsum[t] : 0;
    sm[t] = v;
    __syncthreads();
#pragma unroll
    for (int o = 1; o < 256; o <<= 1) {
        int x = (t >= o) ? sm[t - o] : 0;
        __syncthreads();
        sm[t] += x;
        __syncthreads();
    }
    if (t < nblk) g_bsum[t] = sm[t] - v;         // exclusive
}
__global__ void scan3_k() {
    int idx = blockIdx.x * SCAN_B + threadIdx.x;
    if (idx < NN) g_off[idx] += g_bsum[blockIdx.x];
    if (idx == 0) g_off[NN] = EE;
}

// ---------------- build sorted adjacency (counting-sort fill) --------------
__global__ void build_k(const float* __restrict__ ew) {
    int e = blockIdx.x * blockDim.x + threadIdx.x;
    if (e >= EE) return;
    int r = g_row[e], c = g_col[e];
    int pos = g_off[c] + atomicAdd(&g_fill[c], 1);
    g_src[pos] = r;
    g_w[pos]   = g_dinv[r] * ew[e] * g_dinv[c];
}

// ---------------- SGEMM: g_t = act(A)[N,128] @ W[128,128] ------------------
// 128x128 block tile, 256 threads, 8x8 per-thread register tile,
// inner product via packed fp32 FFMA2 (fma.rn.f32x2) — full fp32 precision,
// 2 FMAs per fma-pipe issue slot.
__global__ void __launch_bounds__(256)
gemm_k(const float* __restrict__ Aext, const float* __restrict__ W,
       int relu_in)
{
    __shared__ __align__(16) float As[128][17];
    __shared__ __align__(16) float Ws[16][132];

    const float* A = Aext ? Aext : g_h;
    float* C = g_t;

    const int tid  = threadIdx.x;
    const int tm   = tid >> 4;         // 0..15
    const int tn   = tid & 15;         // 0..15
    const int row0 = blockIdx.x * 128;

    unsigned long long acc[8][4];      // 8 rows x 4 f32x2 channel pairs
#pragma unroll
    for (int i = 0; i < 8; ++i)
#pragma unroll
        for (int j = 0; j < 4; ++j) acc[i][j] = 0ull;

    const int ar = tid >> 1;           // 0..127
    const int ac = (tid & 1) * 8;      // 0 or 8
    const int wr = tid >> 4;           // 0..15
    const int wc = (tid & 15) * 8;     // 0..120

    for (int k0 = 0; k0 < 128; k0 += 16) {
        float av[8];
        if (row0 + ar < NN) {
            const float4* p =
                (const float4*)(A + (size_t)(row0 + ar) * 128 + k0 + ac);
            float4 u0 = p[0], u1 = p[1];
            av[0] = u0.x; av[1] = u0.y; av[2] = u0.z; av[3] = u0.w;
            av[4] = u1.x; av[5] = u1.y; av[6] = u1.z; av[7] = u1.w;
            if (relu_in) {
#pragma unroll
                for (int j = 0; j < 8; ++j) av[j] = fmaxf(av[j], 0.0f);
            }
        } else {
#pragma unroll
            for (int j = 0; j < 8; ++j) av[j] = 0.0f;
        }
#pragma unroll
        for (int j = 0; j < 8; ++j) As[ar][ac + j] = av[j];

        const float4* wp = (const float4*)(W + (size_t)(k0 + wr) * 128 + wc);
        float4 w0 = wp[0], w1 = wp[1];
        *(float4*)&Ws[wr][wc]     = w0;
        *(float4*)&Ws[wr][wc + 4] = w1;
        __syncthreads();

#pragma unroll
        for (int kk = 0; kk < 16; ++kk) {
            unsigned long long aa[8];
#pragma unroll
            for (int i = 0; i < 8; ++i) aa[i] = pack_dup(As[tm * 8 + i][kk]);
            // 8 consecutive channels = 4 f32x2 pairs, 16B-aligned in Ws
            ulonglong2 b01 = *(const ulonglong2*)&Ws[kk][tn * 8];
            ulonglong2 b23 = *(const ulonglong2*)&Ws[kk][tn * 8 + 4];
            unsigned long long b2[4] = {b01.x, b01.y, b23.x, b23.y};
#pragma unroll
            for (int i = 0; i < 8; ++i)
#pragma unroll
                for (int j = 0; j < 4; ++j)
                    acc[i][j] = ffma2(aa[i], b2[j], acc[i][j]);
        }
        __syncthreads();
    }

#pragma unroll
    for (int i = 0; i < 8; ++i) {
        int m = row0 + tm * 8 + i;
        if (m < NN) {
            float2 p0 = unpack2(acc[i][0]);
            float2 p1 = unpack2(acc[i][1]);
            float2 p2 = unpack2(acc[i][2]);
            float2 p3 = unpack2(acc[i][3]);
            float4* cp = (float4*)(C + (size_t)m * 128 + tn * 8);
            cp[0] = make_float4(p0.x, p0.y, p1.x, p1.y);
            cp[1] = make_float4(p2.x, p2.y, p3.x, p3.y);
        }
    }
}

// ---------------- fused aggregation (gather, no atomics) -------------------
// h[n] = bias + dinv[n]^2 * t[n] + sum_{e in in(n)} w[e] * t[src[e]]
// One warp per node; lane l owns channels [4l, 4l+4). 8-edge unroll for MLP.
__global__ void __launch_bounds__(256)
agg_k(const float* __restrict__ bias)
{
    int warp = (blockIdx.x * blockDim.x + threadIdx.x) >> 5;
    if (warp >= NN) return;
    int lane = threadIdx.x & 31;

    float d = g_dinv[warp];
    float s = d * d;
    float4 acc = ((const float4*)bias)[lane];
    float4 tv  = ((const float4*)(g_t + (size_t)warp * HH))[lane];
    acc.x = fmaf(tv.x, s, acc.x);
    acc.y = fmaf(tv.y, s, acc.y);
    acc.z = fmaf(tv.z, s, acc.z);
    acc.w = fmaf(tv.w, s, acc.w);

    int k   = g_off[warp];
    int end = g_off[warp + 1];

    for (; k + 8 <= end; k += 8) {
        int   r[8]; float w[8]; float4 v[8];
#pragma unroll
        for (int u = 0; u < 8; ++u) { r[u] = g_src[k + u]; w[u] = g_w[k + u]; }
#pragma unroll
        for (int u = 0; u < 8; ++u)
            v[u] = __ldg((const float4*)(g_t + (size_t)r[u] * HH) + lane);
#pragma unroll
        for (int u = 0; u < 8; ++u) {
            acc.x = fmaf(v[u].x, w[u], acc.x);
            acc.y = fmaf(v[u].y, w[u], acc.y);
            acc.z = fmaf(v[u].z, w[u], acc.z);
            acc.w = fmaf(v[u].w, w[u], acc.w);
        }
    }
    for (; k < end; ++k) {
        int   r = g_src[k];
        float w = g_w[k];
        float4 v = __ldg((const float4*)(g_t + (size_t)r * HH) + lane);
        acc.x = fmaf(v.x, w, acc.x); acc.y = fmaf(v.y, w, acc.y);
        acc.z = fmaf(v.z, w, acc.z); acc.w = fmaf(v.w, w, acc.w);
    }

    ((float4*)(g_h + (size_t)warp * HH))[lane] = acc;
}

// ---------------- fused pool + final linear (atomic-free) ------------------
// batch is sorted, so graph g occupies a contiguous node range found by
// binary search. One block per graph: thread t owns channel t, reduces
// relu(h) over the range, then the block reduces the dot with lin_w.
__device__ __forceinline__ int lower_bound_batch(const void* batch, int tgt)
{
    int lo = 0, hi = NN;
    while (lo < hi) {
        int mid = (lo + hi) >> 1;
        long long v = g_b_is64 ? ((const long long*)batch)[mid]
                               : (long long)((const int*)batch)[mid];
        if (v < tgt) lo = mid + 1; else hi = mid;
    }
    return lo;
}

__global__ void poolfinal_k(const void* __restrict__ batch,
                            const float* __restrict__ lw,
                            const float* __restrict__ lb,
                            float* __restrict__ out)
{
    int g = blockIdx.x;       // 64 blocks
    int t = threadIdx.x;      // 128 threads
    __shared__ int se[2];
    if (t == 0) se[0] = lower_bound_batch(batch, g);
    if (t == 1) se[1] = lower_bound_batch(batch, g + 1);
    __syncthreads();
    int s = se[0], e = se[1];

    float sum = 0.0f;
    int r = s;
    for (; r + 4 <= e; r += 4) {
        float v0 = g_h[(size_t)(r + 0) * HH + t];
        float v1 = g_h[(size_t)(r + 1) * HH + t];
        float v2 = g_h[(size_t)(r + 2) * HH + t];
        float v3 = g_h[(size_t)(r + 3) * HH + t];
        sum += fmaxf(v0, 0.0f) + fmaxf(v1, 0.0f)
             + fmaxf(v2, 0.0f) + fmaxf(v3, 0.0f);
    }
    for (; r < e; ++r)
        sum += fmaxf(g_h[(size_t)r * HH + t], 0.0f);

    float inv = 1.0f / fmaxf((float)(e - s), 1.0f);
    float v = sum * inv * lw[t];
#pragma unroll
    for (int o = 16; o > 0; o >>= 1)
        v += __shfl_down_sync(0xffffffffu, v, o);
    __shared__ float sm[4];
    if ((t & 31) == 0) sm[t >> 5] = v;
    __syncthreads();
    if (t == 0) out[g] = sm[0] + sm[1] + sm[2] + sm[3] + lb[0];
}

// ---------------- launcher --------------------------------------------------
extern "C" void kernel_launch(void* const* d_in, const int* in_sizes, int n_in,
                              void* d_out, int out_size)
{
    // Locate inputs by element count (robust to metadata ordering).
    const float* x = nullptr;
    const float* ew = nullptr;
    const void*  ei = nullptr;     // int32 or int64 (auto-detected on device)
    const void*  batch = nullptr;  // int32 or int64
    const float* Wm[3] = {nullptr, nullptr, nullptr};
    const float* v128[4] = {nullptr, nullptr, nullptr, nullptr}; // b1,b2,b3,lin_w
    const float* linb = nullptr;
    int wi = 0, bi = 0;
    for (int i = 0; i < n_in; ++i) {
        int s = in_sizes[i];
        if      (s == NN * HH)  x = (const float*)d_in[i];
        else if (s == EE)       ew = (const float*)d_in[i];
        else if (s == 2 * EE)   ei = d_in[i];
        else if (s == NN)       batch = d_in[i];
        else if (s == HH * HH)  { if (wi < 3) Wm[wi++] = (const float*)d_in[i]; }
        else if (s == HH)       { if (bi < 4) v128[bi++] = (const float*)d_in[i]; }
        else if (s == 1)        linb = (const float*)d_in[i];
    }
    const float* lw = v128[3];
    float* out = (float*)d_out;

    const int TB = 256;
    const int gN  = (NN + TB - 1) / TB;
    const int gE  = (EE + TB - 1) / TB;
    const int gAg = (int)(((long long)NN * 32 + TB - 1) / TB);  // warp/node
    const int gGm = (NN + 127) / 128;
    const int nScanBlk = (NN + SCAN_B - 1) / SCAN_B;            // 196

    // dtype detection + degree count; layer-1 GEMM is independent of the CSR
    // build, so it runs early (also puts it in ncu's fixed capture window).
    detect_k<<<1, 256>>>((const int*)ei, (const int*)batch);
    init_k<<<gN, TB>>>();
    prep_k<<<gE, TB>>>(ei, ew);
    gemm_k<<<gGm, TB>>>(x, Wm[0], 0);          // t = x @ W1
    dinv_k<<<gN, TB>>>();
    scan1_k<<<nScanBlk, SCAN_B>>>();
    scan2_k<<<1, 256>>>(nScanBlk);
    scan3_k<<<nScanBlk, SCAN_B>>>();
    build_k<<<gE, TB>>>(ew);

    // Layer 1 aggregation: h = b1 + dinv^2*t + gather(t)
    agg_k<<<gAg, TB>>>(v128[0]);

    // Layer 2 (input relu fused into GEMM load): t = relu(h) @ W2 ; h = agg
    gemm_k<<<gGm, TB>>>(nullptr, Wm[1], 1);
    agg_k<<<gAg, TB>>>(v128[1]);

    // Layer 3
    gemm_k<<<gGm, TB>>>(nullptr, Wm[2], 1);
    agg_k<<<gAg, TB>>>(v128[2]);

    // Fused pool (relu) + final linear
    poolfinal_k<<<GG, 128>>>(batch, lw, linb, out);
}

// round 9
// speedup vs baseline: 2.8908x; 1.0989x over previous
#include <cuda_runtime.h>
#include <math.h>

// Problem constants (fixed by the reference)
#define NN 100000   // nodes
#define EE 1600000  // edges
#define HH 128      // channels
#define GG 64       // graphs

// ---------------- static device scratch (no allocations allowed) ----------
__device__ __align__(16) float g_t [(size_t)NN * HH];   // h @ W
__device__ __align__(16) float g_h [(size_t)NN * HH];   // layer activations
__device__ float g_dinv[NN];              // deg -> d^{-1/2} (in place)
__device__ int   g_row[EE];
__device__ int   g_col[EE];
// CSR (destination-sorted) adjacency, built once
__device__ int   g_cnt[NN];               // int in-degree
__device__ int   g_off[NN + 1];           // exclusive scan of cnt
__device__ int   g_fill[NN];              // slot fill counters
__device__ int   g_bsum[256];             // block sums for scan
__device__ int   g_src[EE];               // source node, sorted by dst
__device__ float g_w  [EE];               // norm weight, sorted by dst
__device__ int   g_ei_is64;               // dtype flags (auto-detected)
__device__ int   g_b_is64;

// ---------------- f32x2 helpers (Blackwell packed fp32 FMA) ----------------
__device__ __forceinline__ unsigned long long ffma2(
    unsigned long long a, unsigned long long b, unsigned long long c)
{
    unsigned long long d;
    asm("fma.rn.f32x2 %0, %1, %2, %3;" : "=l"(d) : "l"(a), "l"(b), "l"(c));
    return d;
}
__device__ __forceinline__ unsigned long long pack_dup(float a)
{
    unsigned long long r;
    asm("mov.b64 %0, {%1, %1};" : "=l"(r) : "f"(a));
    return r;
}
__device__ __forceinline__ float2 unpack2(unsigned long long v)
{
    float lo, hi;
    asm("mov.b64 {%0, %1}, %2;" : "=f"(lo), "=f"(hi) : "l"(v));
    return make_float2(lo, hi);
}

// ---------------- dtype detection ------------------------------------------
// int64 payloads with values < 2^31 have all odd 32-bit words zero; int32
// payloads (random edge targets / sorted batch ids in the upper half)
// essentially never do. All sampled offsets are in-bounds under either dtype.
__global__ void detect_k(const int* __restrict__ ei32,
                         const int* __restrict__ b32)
{
    int tid = threadIdx.x;                       // 256 threads, 1 block
    int je = 1 + 12500 * tid;                    // odd words across [1, 2*EE)
    int ei_nz = (ei32[je] != 0);
    int jb = 50001 + 194 * tid;                  // odd words, upper half of N
    int b_nz = (b32[jb] != 0);
    int any_ei = __syncthreads_or(ei_nz);
    int any_b  = __syncthreads_or(b_nz);
    if (tid == 0) {
        g_ei_is64 = (any_ei == 0);
        g_b_is64  = (any_b  == 0);
    }
}

// ---------------- init ------------------------------------------------------
__global__ void init_k() {
    int i = blockIdx.x * blockDim.x + threadIdx.x;
    if (i < NN) { g_dinv[i] = 1.0f; g_cnt[i] = 0; g_fill[i] = 0; }
}

// ---------------- edge prep: decode indices, weighted degree, int count ----
__global__ void prep_k(const void* __restrict__ ei,
                       const float* __restrict__ ew) {
    int e = blockIdx.x * blockDim.x + threadIdx.x;
    if (e >= EE) return;
    int r, c;
    if (g_ei_is64) {
        const long long* p = (const long long*)ei;
        r = (int)p[e]; c = (int)p[EE + e];
    } else {
        const int* p = (const int*)ei;
        r = p[e]; c = p[EE + e];
    }
    g_row[e] = r;
    g_col[e] = c;
    atomicAdd(&g_dinv[c], ew[e]);           // weighted in-degree
    atomicAdd(&g_cnt[c], 1);                // integer in-degree (for CSR)
}

__global__ void dinv_k() {
    int i = blockIdx.x * blockDim.x + threadIdx.x;
    if (i >= NN) return;
    float d = g_dinv[i];
    g_dinv[i] = (d > 0.0f) ? rsqrtf(d) : 0.0f;
}

// ---------------- 3-kernel exclusive scan of g_cnt -> g_off ----------------
#define SCAN_B 512
__global__ void scan1_k() {      // per-block exclusive scan + block totals
    __shared__ int sm[SCAN_B];
    int t = threadIdx.x;
    int idx = blockIdx.x * SCAN_B + t;
    int v = (idx < NN) ? g_cnt[idx] : 0;
    sm[t] = v;
    __syncthreads();
#pragma unroll
    for (int o = 1; o < SCAN_B; o <<= 1) {
        int x = (t >= o) ? sm[t - o] : 0;
        __syncthreads();
        sm[t] += x;
        __syncthreads();
    }
    if (idx < NN) g_off[idx] = sm[t] - v;        // exclusive
    if (t == SCAN_B - 1) g_bsum[blockIdx.x] = sm[t];
}
__global__ void scan2_k(int nblk) {  // single block: scan block totals
    __shared__ int sm[256];
    int t = threadIdx.x;
    int v = (t < nblk) ? g_bsum[t] : 0;
    sm[t] = v;
    __syncthreads();
#pragma unroll
    for (int o = 1; o < 256; o <<= 1) {
        int x = (t >= o) ? sm[t - o] : 0;
        __syncthreads();
        sm[t] += x;
        __syncthreads();
    }
    if (t < nblk) g_bsum[t] = sm[t] - v;         // exclusive
}
__global__ void scan3_k() {
    int idx = blockIdx.x * SCAN_B + threadIdx.x;
    if (idx < NN) g_off[idx] += g_bsum[blockIdx.x];
    if (idx == 0) g_off[NN] = EE;
}

// ---------------- build sorted adjacency (counting-sort fill) --------------
__global__ void build_k(const float* __restrict__ ew) {
    int e = blockIdx.x * blockDim.x + threadIdx.x;
    if (e >= EE) return;
    int r = g_row[e], c = g_col[e];
    int pos = g_off[c] + atomicAdd(&g_fill[c], 1);
    g_src[pos] = r;
    g_w[pos]   = g_dinv[r] * ew[e] * g_dinv[c];
}

// ---------------- SGEMM: g_t = act(A)[N,128] @ W[128,128] ------------------
// 128x128 block tile, 256 threads, 8x8 per-thread register tile.
// A tile stored TRANSPOSED in smem ([k][m]) so the inner loop reads both
// operands as broadcast LDS.128; inner product via packed fp32 FFMA2.
// 2 CTAs/SM forced via launch bounds (128-reg cap) for latency hiding.
__global__ void __launch_bounds__(256, 2)
gemm_k(const float* __restrict__ Aext, const float* __restrict__ W,
       int relu_in)
{
    __shared__ __align__(16) float As[16][132];   // [k][m], transposed
    __shared__ __align__(16) float Ws[16][132];   // [k][n]

    const float* A = Aext ? Aext : g_h;
    float* C = g_t;

    const int tid  = threadIdx.x;
    const int tm   = tid >> 4;         // 0..15
    const int tn   = tid & 15;         // 0..15
    const int row0 = blockIdx.x * 128;

    unsigned long long acc[8][4];      // 8 rows x 4 f32x2 channel pairs
#pragma unroll
    for (int i = 0; i < 8; ++i)
#pragma unroll
        for (int j = 0; j < 4; ++j) acc[i][j] = 0ull;

    const int ar = tid >> 1;           // 0..127  (A row this thread stages)
    const int ac = (tid & 1) * 8;      // 0 or 8  (A k-chunk col base)
    const int wr = tid >> 4;           // 0..15
    const int wc = (tid & 15) * 8;     // 0..120

    for (int k0 = 0; k0 < 128; k0 += 16) {
        float av[8];
        if (row0 + ar < NN) {
            const float4* p =
                (const float4*)(A + (size_t)(row0 + ar) * 128 + k0 + ac);
            float4 u0 = p[0], u1 = p[1];
            av[0] = u0.x; av[1] = u0.y; av[2] = u0.z; av[3] = u0.w;
            av[4] = u1.x; av[5] = u1.y; av[6] = u1.z; av[7] = u1.w;
            if (relu_in) {
#pragma unroll
                for (int j = 0; j < 8; ++j) av[j] = fmaxf(av[j], 0.0f);
            }
        } else {
#pragma unroll
            for (int j = 0; j < 8; ++j) av[j] = 0.0f;
        }
#pragma unroll
        for (int j = 0; j < 8; ++j) As[ac + j][ar] = av[j];   // transpose

        const float4* wp = (const float4*)(W + (size_t)(k0 + wr) * 128 + wc);
        float4 w0 = wp[0], w1 = wp[1];
        *(float4*)&Ws[wr][wc]     = w0;
        *(float4*)&Ws[wr][wc + 4] = w1;
        __syncthreads();

#pragma unroll
        for (int kk = 0; kk < 16; ++kk) {
            // broadcast vector loads: 16 threads share each address
            float4 a0 = *(const float4*)&As[kk][tm * 8];
            float4 a1 = *(const float4*)&As[kk][tm * 8 + 4];
            ulonglong2 b01 = *(const ulonglong2*)&Ws[kk][tn * 8];
            ulonglong2 b23 = *(const ulonglong2*)&Ws[kk][tn * 8 + 4];
            unsigned long long b2[4] = {b01.x, b01.y, b23.x, b23.y};
            float a[8] = {a0.x, a0.y, a0.z, a0.w, a1.x, a1.y, a1.z, a1.w};
#pragma unroll
            for (int i = 0; i < 8; ++i) {
                unsigned long long ap = pack_dup(a[i]);
#pragma unroll
                for (int j = 0; j < 4; ++j)
                    acc[i][j] = ffma2(ap, b2[j], acc[i][j]);
            }
        }
        __syncthreads();
    }

#pragma unroll
    for (int i = 0; i < 8; ++i) {
        int m = row0 + tm * 8 + i;
        if (m < NN) {
            float2 p0 = unpack2(acc[i][0]);
            float2 p1 = unpack2(acc[i][1]);
            float2 p2 = unpack2(acc[i][2]);
            float2 p3 = unpack2(acc[i][3]);
            float4* cp = (float4*)(C + (size_t)m * 128 + tn * 8);
            cp[0] = make_float4(p0.x, p0.y, p1.x, p1.y);
            cp[1] = make_float4(p2.x, p2.y, p3.x, p3.y);
        }
    }
}

// ---------------- fused aggregation (gather, no atomics) -------------------
// h[n] = bias + dinv[n]^2 * t[n] + sum_{e in in(n)} w[e] * t[src[e]]
// One warp per node; lane l owns channels [4l, 4l+4). 8-edge unroll for MLP.
__global__ void __launch_bounds__(256)
agg_k(const float* __restrict__ bias)
{
    int warp = (blockIdx.x * blockDim.x + threadIdx.x) >> 5;
    if (warp >= NN) return;
    int lane = threadIdx.x & 31;

    float d = g_dinv[warp];
    float s = d * d;
    float4 acc = ((const float4*)bias)[lane];
    float4 tv  = ((const float4*)(g_t + (size_t)warp * HH))[lane];
    acc.x = fmaf(tv.x, s, acc.x);
    acc.y = fmaf(tv.y, s, acc.y);
    acc.z = fmaf(tv.z, s, acc.z);
    acc.w = fmaf(tv.w, s, acc.w);

    int k   = g_off[warp];
    int end = g_off[warp + 1];

    for (; k + 8 <= end; k += 8) {
        int   r[8]; float w[8]; float4 v[8];
#pragma unroll
        for (int u = 0; u < 8; ++u) { r[u] = g_src[k + u]; w[u] = g_w[k + u]; }
#pragma unroll
        for (int u = 0; u < 8; ++u)
            v[u] = __ldg((const float4*)(g_t + (size_t)r[u] * HH) + lane);
#pragma unroll
        for (int u = 0; u < 8; ++u) {
            acc.x = fmaf(v[u].x, w[u], acc.x);
            acc.y = fmaf(v[u].y, w[u], acc.y);
            acc.z = fmaf(v[u].z, w[u], acc.z);
            acc.w = fmaf(v[u].w, w[u], acc.w);
        }
    }
    for (; k < end; ++k) {
        int   r = g_src[k];
        float w = g_w[k];
        float4 v = __ldg((const float4*)(g_t + (size_t)r * HH) + lane);
        acc.x = fmaf(v.x, w, acc.x); acc.y = fmaf(v.y, w, acc.y);
        acc.z = fmaf(v.z, w, acc.z); acc.w = fmaf(v.w, w, acc.w);
    }

    ((float4*)(g_h + (size_t)warp * HH))[lane] = acc;
}

// ---------------- fused pool + final linear (atomic-free) ------------------
// batch is sorted, so graph g occupies a contiguous node range found by
// binary search. One block per graph: thread t owns channel t, reduces
// relu(h) over the range, then the block reduces the dot with lin_w.
__device__ __forceinline__ int lower_bound_batch(const void* batch, int tgt)
{
    int lo = 0, hi = NN;
    while (lo < hi) {
        int mid = (lo + hi) >> 1;
        long long v = g_b_is64 ? ((const long long*)batch)[mid]
                               : (long long)((const int*)batch)[mid];
        if (v < tgt) lo = mid + 1; else hi = mid;
    }
    return lo;
}

__global__ void poolfinal_k(const void* __restrict__ batch,
                            const float* __restrict__ lw,
                            const float* __restrict__ lb,
                            float* __restrict__ out)
{
    int g = blockIdx.x;       // 64 blocks
    int t = threadIdx.x;      // 128 threads
    __shared__ int se[2];
    if (t == 0) se[0] = lower_bound_batch(batch, g);
    if (t == 1) se[1] = lower_bound_batch(batch, g + 1);
    __syncthreads();
    int s = se[0], e = se[1];

    float sum = 0.0f;
    int r = s;
    for (; r + 4 <= e; r += 4) {
        float v0 = g_h[(size_t)(r + 0) * HH + t];
        float v1 = g_h[(size_t)(r + 1) * HH + t];
        float v2 = g_h[(size_t)(r + 2) * HH + t];
        float v3 = g_h[(size_t)(r + 3) * HH + t];
        sum += fmaxf(v0, 0.0f) + fmaxf(v1, 0.0f)
             + fmaxf(v2, 0.0f) + fmaxf(v3, 0.0f);
    }
    for (; r < e; ++r)
        sum += fmaxf(g_h[(size_t)r * HH + t], 0.0f);

    float inv = 1.0f / fmaxf((float)(e - s), 1.0f);
    float v = sum * inv * lw[t];
#pragma unroll
    for (int o = 16; o > 0; o >>= 1)
        v += __shfl_down_sync(0xffffffffu, v, o);
    __shared__ float sm[4];
    if ((t & 31) == 0) sm[t >> 5] = v;
    __syncthreads();
    if (t == 0) out[g] = sm[0] + sm[1] + sm[2] + sm[3] + lb[0];
}

// ---------------- launcher --------------------------------------------------
extern "C" void kernel_launch(void* const* d_in, const int* in_sizes, int n_in,
                              void* d_out, int out_size)
{
    // Locate inputs by element count (robust to metadata ordering).
    const float* x = nullptr;
    const float* ew = nullptr;
    const void*  ei = nullptr;     // int32 or int64 (auto-detected on device)
    const void*  batch = nullptr;  // int32 or int64
    const float* Wm[3] = {nullptr, nullptr, nullptr};
    const float* v128[4] = {nullptr, nullptr, nullptr, nullptr}; // b1,b2,b3,lin_w
    const float* linb = nullptr;
    int wi = 0, bi = 0;
    for (int i = 0; i < n_in; ++i) {
        int s = in_sizes[i];
        if      (s == NN * HH)  x = (const float*)d_in[i];
        else if (s == EE)       ew = (const float*)d_in[i];
        else if (s == 2 * EE)   ei = d_in[i];
        else if (s == NN)       batch = d_in[i];
        else if (s == HH * HH)  { if (wi < 3) Wm[wi++] = (const float*)d_in[i]; }
        else if (s == HH)       { if (bi < 4) v128[bi++] = (const float*)d_in[i]; }
        else if (s == 1)        linb = (const float*)d_in[i];
    }
    const float* lw = v128[3];
    float* out = (float*)d_out;

    const int TB = 256;
    const int gN  = (NN + TB - 1) / TB;
    const int gE  = (EE + TB - 1) / TB;
    const int gAg = (int)(((long long)NN * 32 + TB - 1) / TB);  // warp/node
    const int gGm = (NN + 127) / 128;
    const int nScanBlk = (NN + SCAN_B - 1) / SCAN_B;            // 196

    // dtype detection + degree count; layer-1 GEMM is independent of the CSR
    // build, so it runs early (also puts it in ncu's fixed capture window).
    detect_k<<<1, 256>>>((const int*)ei, (const int*)batch);
    init_k<<<gN, TB>>>();
    prep_k<<<gE, TB>>>(ei, ew);
    gemm_k<<<gGm, TB>>>(x, Wm[0], 0);          // t = x @ W1
    dinv_k<<<gN, TB>>>();
    scan1_k<<<nScanBlk, SCAN_B>>>();
    scan2_k<<<1, 256>>>(nScanBlk);
    scan3_k<<<nScanBlk, SCAN_B>>>();
    build_k<<<gE, TB>>>(ew);

    // Layer 1 aggregation: h = b1 + dinv^2*t + gather(t)
    agg_k<<<gAg, TB>>>(v128[0]);

    // Layer 2 (input relu fused into GEMM load): t = relu(h) @ W2 ; h = agg
    gemm_k<<<gGm, TB>>>(nullptr, Wm[1], 1);
    agg_k<<<gAg, TB>>>(v128[1]);

    // Layer 3
    gemm_k<<<gGm, TB>>>(nullptr, Wm[2], 1);
    agg_k<<<gAg, TB>>>(v128[2]);

    // Fused pool (relu) + final linear
    poolfinal_k<<<GG, 128>>>(batch, lw, linb, out);
}

// round 10
// speedup vs baseline: 3.0396x; 1.0515x over previous
#include <cuda_runtime.h>
#include <cuda_fp16.h>
#include <math.h>

// Problem constants (fixed by the reference)
#define NN 100000   // nodes
#define EE 1600000  // edges
#define HH 128      // channels
#define GG 64       // graphs

// ---------------- static device scratch (no allocations allowed) ----------
__device__ __align__(16) float  g_t [(size_t)NN * HH];  // h @ W (fp32)
__device__ __align__(16) __half g_th[(size_t)NN * HH];  // h @ W (fp16 copy)
__device__ __align__(16) float  g_h [(size_t)NN * HH];  // layer activations
__device__ float g_dinv[NN];              // deg -> d^{-1/2} (in place)
__device__ int   g_row[EE];
__device__ int   g_col[EE];
// CSR (destination-sorted) adjacency, built once
__device__ int   g_cnt[NN];               // int in-degree
__device__ int   g_off[NN + 1];           // exclusive scan of cnt
__device__ int   g_fill[NN];              // slot fill counters
__device__ int   g_bsum[256];             // block sums for scan
__device__ int   g_src[EE];               // source node, sorted by dst
__device__ float g_w  [EE];               // norm weight, sorted by dst
__device__ int   g_ei_is64;               // dtype flags (auto-detected)
__device__ int   g_b_is64;

// ---------------- f32x2 helpers (Blackwell packed fp32 FMA) ----------------
__device__ __forceinline__ unsigned long long ffma2(
    unsigned long long a, unsigned long long b, unsigned long long c)
{
    unsigned long long d;
    asm("fma.rn.f32x2 %0, %1, %2, %3;" : "=l"(d) : "l"(a), "l"(b), "l"(c));
    return d;
}
__device__ __forceinline__ unsigned long long pack_dup(float a)
{
    unsigned long long r;
    asm("mov.b64 %0, {%1, %1};" : "=l"(r) : "f"(a));
    return r;
}
__device__ __forceinline__ float2 unpack2(unsigned long long v)
{
    float lo, hi;
    asm("mov.b64 {%0, %1}, %2;" : "=f"(lo), "=f"(hi) : "l"(v));
    return make_float2(lo, hi);
}

// ---------------- dtype detection ------------------------------------------
// int64 payloads with values < 2^31 have all odd 32-bit words zero; int32
// payloads (random edge targets / sorted batch ids in the upper half)
// essentially never do. All sampled offsets are in-bounds under either dtype.
__global__ void detect_k(const int* __restrict__ ei32,
                         const int* __restrict__ b32)
{
    int tid = threadIdx.x;                       // 256 threads, 1 block
    int je = 1 + 12500 * tid;                    // odd words across [1, 2*EE)
    int ei_nz = (ei32[je] != 0);
    int jb = 50001 + 194 * tid;                  // odd words, upper half of N
    int b_nz = (b32[jb] != 0);
    int any_ei = __syncthreads_or(ei_nz);
    int any_b  = __syncthreads_or(b_nz);
    if (tid == 0) {
        g_ei_is64 = (any_ei == 0);
        g_b_is64  = (any_b  == 0);
    }
}

// ---------------- init ------------------------------------------------------
__global__ void init_k() {
    int i = blockIdx.x * blockDim.x + threadIdx.x;
    if (i < NN) { g_dinv[i] = 1.0f; g_cnt[i] = 0; g_fill[i] = 0; }
}

// ---------------- edge prep: decode indices, weighted degree, int count ----
__global__ void prep_k(const void* __restrict__ ei,
                       const float* __restrict__ ew) {
    int e = blockIdx.x * blockDim.x + threadIdx.x;
    if (e >= EE) return;
    int r, c;
    if (g_ei_is64) {
        const long long* p = (const long long*)ei;
        r = (int)p[e]; c = (int)p[EE + e];
    } else {
        const int* p = (const int*)ei;
        r = p[e]; c = p[EE + e];
    }
    g_row[e] = r;
    g_col[e] = c;
    atomicAdd(&g_dinv[c], ew[e]);           // weighted in-degree
    atomicAdd(&g_cnt[c], 1);                // integer in-degree (for CSR)
}

__global__ void dinv_k() {
    int i = blockIdx.x * blockDim.x + threadIdx.x;
    if (i >= NN) return;
    float d = g_dinv[i];
    g_dinv[i] = (d > 0.0f) ? rsqrtf(d) : 0.0f;
}

// ---------------- 3-kernel exclusive scan of g_cnt -> g_off ----------------
#define SCAN_B 512
__global__ void scan1_k() {      // per-block exclusive scan + block totals
    __shared__ int sm[SCAN_B];
    int t = threadIdx.x;
    int idx = blockIdx.x * SCAN_B + t;
    int v = (idx < NN) ? g_cnt[idx] : 0;
    sm[t] = v;
    __syncthreads();
#pragma unroll
    for (int o = 1; o < SCAN_B; o <<= 1) {
        int x = (t >= o) ? sm[t - o] : 0;
        __syncthreads();
        sm[t] += x;
        __syncthreads();
    }
    if (idx < NN) g_off[idx] = sm[t] - v;        // exclusive
    if (t == SCAN_B - 1) g_bsum[blockIdx.x] = sm[t];
}
__global__ void scan2_k(int nblk) {  // single block: scan block totals
    __shared__ int sm[256];
    int t = threadIdx.x;
    int v = (t < nblk) ? g_bsum[t] : 0;
    sm[t] = v;
    __syncthreads();
#pragma unroll
    for (int o = 1; o < 256; o <<= 1) {
        int x = (t >= o) ? sm[t - o] : 0;
        __syncthreads();
        sm[t] += x;
        __syncthreads();
    }
    if (t < nblk) g_bsum[t] = sm[t] - v;         // exclusive
}
__global__ void scan3_k() {
    int idx = blockIdx.x * SCAN_B + threadIdx.x;
    if (idx < NN) g_off[idx] += g_bsum[blockIdx.x];
    if (idx == 0) g_off[NN] = EE;
}

// ---------------- build sorted adjacency (counting-sort fill) --------------
__global__ void build_k(const float* __restrict__ ew) {
    int e = blockIdx.x * blockDim.x + threadIdx.x;
    if (e >= EE) return;
    int r = g_row[e], c = g_col[e];
    int pos = g_off[c] + atomicAdd(&g_fill[c], 1);
    g_src[pos] = r;
    g_w[pos]   = g_dinv[r] * ew[e] * g_dinv[c];
}

// ---------------- SGEMM: g_t/g_th = act(A)[N,128] @ W[128,128] -------------
// 128x128 block tile, 256 threads, 8x8 per-thread register tile.
// Double-buffered smem (one barrier per k-chunk) + register prefetch of the
// next chunk; A tile transposed in smem so all operand reads are broadcast
// LDS.128; inner product via packed fp32 FFMA2. Epilogue writes fp32 result
// plus an fp16 copy used by the bandwidth-bound message gather.
__global__ void __launch_bounds__(256, 2)
gemm_k(const float* __restrict__ Aext, const float* __restrict__ W,
       int relu_in)
{
    __shared__ __align__(16) float As[2][16][132];   // [buf][k][m]
    __shared__ __align__(16) float Ws[2][16][132];   // [buf][k][n]

    const float* A = Aext ? Aext : g_h;

    const int tid  = threadIdx.x;
    const int tm   = tid >> 4;         // 0..15
    const int tn   = tid & 15;         // 0..15
    const int row0 = blockIdx.x * 128;

    unsigned long long acc[8][4];      // 8 rows x 4 f32x2 channel pairs
#pragma unroll
    for (int i = 0; i < 8; ++i)
#pragma unroll
        for (int j = 0; j < 4; ++j) acc[i][j] = 0ull;

    const int ar = tid >> 1;           // 0..127  (A row this thread stages)
    const int ac = (tid & 1) * 8;      // 0 or 8  (A k-chunk col base)
    const int wr = tid >> 4;           // 0..15
    const int wc = (tid & 15) * 8;     // 0..120
    const bool arow_ok = (row0 + ar < NN);
    const float* arow = A + (size_t)(row0 + ar) * 128 + ac;

    // prologue: stage chunk 0
    {
        float av[8];
        if (arow_ok) {
            const float4* p = (const float4*)arow;
            float4 u0 = p[0], u1 = p[1];
            av[0] = u0.x; av[1] = u0.y; av[2] = u0.z; av[3] = u0.w;
            av[4] = u1.x; av[5] = u1.y; av[6] = u1.z; av[7] = u1.w;
            if (relu_in) {
#pragma unroll
                for (int j = 0; j < 8; ++j) av[j] = fmaxf(av[j], 0.0f);
            }
        } else {
#pragma unroll
            for (int j = 0; j < 8; ++j) av[j] = 0.0f;
        }
#pragma unroll
        for (int j = 0; j < 8; ++j) As[0][ac + j][ar] = av[j];
        const float4* wp = (const float4*)(W + (size_t)wr * 128 + wc);
        *(float4*)&Ws[0][wr][wc]     = wp[0];
        *(float4*)&Ws[0][wr][wc + 4] = wp[1];
        __syncthreads();
    }

#pragma unroll 1
    for (int k0 = 0; k0 < 8; ++k0) {
        const int cur = k0 & 1;
        const bool has_next = (k0 < 7);

        // prefetch next chunk into registers (overlaps with compute below)
        float nav[8];
        float4 nw0, nw1;
        if (has_next) {
            int kb = (k0 + 1) * 16;
            if (arow_ok) {
                const float4* p = (const float4*)(arow + kb);
                float4 u0 = p[0], u1 = p[1];
                nav[0] = u0.x; nav[1] = u0.y; nav[2] = u0.z; nav[3] = u0.w;
                nav[4] = u1.x; nav[5] = u1.y; nav[6] = u1.z; nav[7] = u1.w;
                if (relu_in) {
#pragma unroll
                    for (int j = 0; j < 8; ++j) nav[j] = fmaxf(nav[j], 0.0f);
                }
            } else {
#pragma unroll
                for (int j = 0; j < 8; ++j) nav[j] = 0.0f;
            }
            const float4* wp =
                (const float4*)(W + (size_t)(kb + wr) * 128 + wc);
            nw0 = wp[0];
            nw1 = wp[1];
        }

        // compute on current buffer
#pragma unroll
        for (int kk = 0; kk < 16; ++kk) {
            float4 a0 = *(const float4*)&As[cur][kk][tm * 8];
            float4 a1 = *(const float4*)&As[cur][kk][tm * 8 + 4];
            ulonglong2 b01 = *(const ulonglong2*)&Ws[cur][kk][tn * 8];
            ulonglong2 b23 = *(const ulonglong2*)&Ws[cur][kk][tn * 8 + 4];
            unsigned long long b2[4] = {b01.x, b01.y, b23.x, b23.y};
            float a[8] = {a0.x, a0.y, a0.z, a0.w, a1.x, a1.y, a1.z, a1.w};
#pragma unroll
            for (int i = 0; i < 8; ++i) {
                unsigned long long ap = pack_dup(a[i]);
#pragma unroll
                for (int j = 0; j < 4; ++j)
                    acc[i][j] = ffma2(ap, b2[j], acc[i][j]);
            }
        }

        if (has_next) {
            const int nb = cur ^ 1;
#pragma unroll
            for (int j = 0; j < 8; ++j) As[nb][ac + j][ar] = nav[j];
            *(float4*)&Ws[nb][wr][wc]     = nw0;
            *(float4*)&Ws[nb][wr][wc + 4] = nw1;
            __syncthreads();
        }
    }

#pragma unroll
    for (int i = 0; i < 8; ++i) {
        int m = row0 + tm * 8 + i;
        if (m < NN) {
            float2 p0 = unpack2(acc[i][0]);
            float2 p1 = unpack2(acc[i][1]);
            float2 p2 = unpack2(acc[i][2]);
            float2 p3 = unpack2(acc[i][3]);
            float4* cp = (float4*)(g_t + (size_t)m * 128 + tn * 8);
            cp[0] = make_float4(p0.x, p0.y, p1.x, p1.y);
            cp[1] = make_float4(p2.x, p2.y, p3.x, p3.y);
            union { __half2 h[4]; uint4 u; } cv;
            cv.h[0] = __float22half2_rn(p0);
            cv.h[1] = __float22half2_rn(p1);
            cv.h[2] = __float22half2_rn(p2);
            cv.h[3] = __float22half2_rn(p3);
            *(uint4*)(g_th + (size_t)m * 128 + tn * 8) = cv.u;
        }
    }
}

// ---------------- fused aggregation (gather, no atomics) -------------------
// h[n] = bias + dinv[n]^2 * t_fp32[n] + sum_{e in in(n)} w[e] * t_fp16[src[e]]
// One warp per node; lane l owns channels [4l, 4l+4). fp16 message tier
// halves the random-gather L2 traffic; accumulation stays fp32.
__global__ void __launch_bounds__(256)
agg_k(const float* __restrict__ bias)
{
    int warp = (blockIdx.x * blockDim.x + threadIdx.x) >> 5;
    if (warp >= NN) return;
    int lane = threadIdx.x & 31;

    float d = g_dinv[warp];
    float s = d * d;
    float4 acc = ((const float4*)bias)[lane];
    float4 tv  = ((const float4*)(g_t + (size_t)warp * HH))[lane];
    acc.x = fmaf(tv.x, s, acc.x);
    acc.y = fmaf(tv.y, s, acc.y);
    acc.z = fmaf(tv.z, s, acc.z);
    acc.w = fmaf(tv.w, s, acc.w);

    int k   = g_off[warp];
    int end = g_off[warp + 1];

    for (; k + 8 <= end; k += 8) {
        int r[8]; float w[8]; uint2 q[8];
#pragma unroll
        for (int u = 0; u < 8; ++u) { r[u] = g_src[k + u]; w[u] = g_w[k + u]; }
#pragma unroll
        for (int u = 0; u < 8; ++u)
            q[u] = __ldg((const uint2*)(g_th + (size_t)r[u] * HH) + lane);
#pragma unroll
        for (int u = 0; u < 8; ++u) {
            float2 f0 = __half22float2(*(const __half2*)&q[u].x);
            float2 f1 = __half22float2(*(const __half2*)&q[u].y);
            acc.x = fmaf(f0.x, w[u], acc.x);
            acc.y = fmaf(f0.y, w[u], acc.y);
            acc.z = fmaf(f1.x, w[u], acc.z);
            acc.w = fmaf(f1.y, w[u], acc.w);
        }
    }
    for (; k < end; ++k) {
        int   r = g_src[k];
        float w = g_w[k];
        uint2 q = __ldg((const uint2*)(g_th + (size_t)r * HH) + lane);
        float2 f0 = __half22float2(*(const __half2*)&q.x);
        float2 f1 = __half22float2(*(const __half2*)&q.y);
        acc.x = fmaf(f0.x, w, acc.x); acc.y = fmaf(f0.y, w, acc.y);
        acc.z = fmaf(f1.x, w, acc.z); acc.w = fmaf(f1.y, w, acc.w);
    }

    ((float4*)(g_h + (size_t)warp * HH))[lane] = acc;
}

// ---------------- fused pool + final linear (atomic-free) ------------------
// batch is sorted, so graph g occupies a contiguous node range found by
// binary search. One block per graph: thread t owns channel t, reduces
// relu(h) over the range, then the block reduces the dot with lin_w.
__device__ __forceinline__ int lower_bound_batch(const void* batch, int tgt)
{
    int lo = 0, hi = NN;
    while (lo < hi) {
        int mid = (lo + hi) >> 1;
        long long v = g_b_is64 ? ((const long long*)batch)[mid]
                               : (long long)((const int*)batch)[mid];
        if (v < tgt) lo = mid + 1; else hi = mid;
    }
    return lo;
}

__global__ void poolfinal_k(const void* __restrict__ batch,
                            const float* __restrict__ lw,
                            const float* __restrict__ lb,
                            float* __restrict__ out)
{
    int g = blockIdx.x;       // 64 blocks
    int t = threadIdx.x;      // 128 threads
    __shared__ int se[2];
    if (t == 0) se[0] = lower_bound_batch(batch, g);
    if (t == 1) se[1] = lower_bound_batch(batch, g + 1);
    __syncthreads();
    int s = se[0], e = se[1];

    float sum = 0.0f;
    int r = s;
    for (; r + 4 <= e; r += 4) {
        float v0 = g_h[(size_t)(r + 0) * HH + t];
        float v1 = g_h[(size_t)(r + 1) * HH + t];
        float v2 = g_h[(size_t)(r + 2) * HH + t];
        float v3 = g_h[(size_t)(r + 3) * HH + t];
        sum += fmaxf(v0, 0.0f) + fmaxf(v1, 0.0f)
             + fmaxf(v2, 0.0f) + fmaxf(v3, 0.0f);
    }
    for (; r < e; ++r)
        sum += fmaxf(g_h[(size_t)r * HH + t], 0.0f);

    float inv = 1.0f / fmaxf((float)(e - s), 1.0f);
    float v = sum * inv * lw[t];
#pragma unroll
    for (int o = 16; o > 0; o >>= 1)
        v += __shfl_down_sync(0xffffffffu, v, o);
    __shared__ float sm[4];
    if ((t & 31) == 0) sm[t >> 5] = v;
    __syncthreads();
    if (t == 0) out[g] = sm[0] + sm[1] + sm[2] + sm[3] + lb[0];
}

// ---------------- launcher --------------------------------------------------
extern "C" void kernel_launch(void* const* d_in, const int* in_sizes, int n_in,
                              void* d_out, int out_size)
{
    // Locate inputs by element count (robust to metadata ordering).
    const float* x = nullptr;
    const float* ew = nullptr;
    const void*  ei = nullptr;     // int32 or int64 (auto-detected on device)
    const void*  batch = nullptr;  // int32 or int64
    const float* Wm[3] = {nullptr, nullptr, nullptr};
    const float* v128[4] = {nullptr, nullptr, nullptr, nullptr}; // b1,b2,b3,lin_w
    const float* linb = nullptr;
    int wi = 0, bi = 0;
    for (int i = 0; i < n_in; ++i) {
        int s = in_sizes[i];
        if      (s == NN * HH)  x = (const float*)d_in[i];
        else if (s == EE)       ew = (const float*)d_in[i];
        else if (s == 2 * EE)   ei = d_in[i];
        else if (s == NN)       batch = d_in[i];
        else if (s == HH * HH)  { if (wi < 3) Wm[wi++] = (const float*)d_in[i]; }
        else if (s == HH)       { if (bi < 4) v128[bi++] = (const float*)d_in[i]; }
        else if (s == 1)        linb = (const float*)d_in[i];
    }
    const float* lw = v128[3];
    float* out = (float*)d_out;

    const int TB = 256;
    const int gN  = (NN + TB - 1) / TB;
    const int gE  = (EE + TB - 1) / TB;
    const int gAg = (int)(((long long)NN * 32 + TB - 1) / TB);  // warp/node
    const int gGm = (NN + 127) / 128;
    const int nScanBlk = (NN + SCAN_B - 1) / SCAN_B;            // 196

    // dtype detection + degree count; layer-1 GEMM is independent of the CSR
    // build, so it runs early (also puts it in ncu's fixed capture window).
    detect_k<<<1, 256>>>((const int*)ei, (const int*)batch);
    init_k<<<gN, TB>>>();
    prep_k<<<gE, TB>>>(ei, ew);
    gemm_k<<<gGm, TB>>>(x, Wm[0], 0);          // t = x @ W1
    dinv_k<<<gN, TB>>>();
    scan1_k<<<nScanBlk, SCAN_B>>>();
    scan2_k<<<1, 256>>>(nScanBlk);
    scan3_k<<<nScanBlk, SCAN_B>>>();
    build_k<<<gE, TB>>>(ew);

    // Layer 1 aggregation: h = b1 + dinv^2*t + gather(t)
    agg_k<<<gAg, TB>>>(v128[0]);

    // Layer 2 (input relu fused into GEMM load): t = relu(h) @ W2 ; h = agg
    gemm_k<<<gGm, TB>>>(nullptr, Wm[1], 1);
    agg_k<<<gAg, TB>>>(v128[1]);

    // Layer 3
    gemm_k<<<gGm, TB>>>(nullptr, Wm[2], 1);
    agg_k<<<gAg, TB>>>(v128[2]);

    // Fused pool (relu) + final linear
    poolfinal_k<<<GG, 128>>>(batch, lw, linb, out);
}

// round 11
// speedup vs baseline: 4.8072x; 1.5815x over previous
#include <cuda_runtime.h>
#include <cuda_fp16.h>
#include <math.h>

// Problem constants (fixed by the reference)
#define NN 100000   // nodes
#define EE 1600000  // edges
#define HH 128      // channels
#define GG 64       // graphs

// ---------------- static device scratch (no allocations allowed) ----------
// fp16 activation ping-pong (fp32 math, fp16 storage):
//   g_ah : GEMM input  (relu'd activations / converted x), padded 128 rows
//   g_th : GEMM output (transformed features; agg gathers from here)
__device__ __align__(16) __half g_ah[(size_t)(NN + 128) * HH];
__device__ __align__(16) __half g_th[(size_t)NN * HH];
__device__ __align__(16) uint2  g_bw[16 * 8 * 32];   // repacked W B-fragments
__device__ float g_dinv[NN];              // deg -> d^{-1/2} (in place)
__device__ int   g_row[EE];
__device__ int   g_col[EE];
// CSR (destination-sorted) adjacency, built once
__device__ int   g_cnt[NN];               // int in-degree
__device__ int   g_off[NN + 1];           // exclusive scan of cnt
__device__ int   g_fill[NN];              // slot fill counters
__device__ int   g_bsum[256];             // block sums for scan
__device__ int   g_src[EE];               // source node, sorted by dst
__device__ float g_w  [EE];               // norm weight, sorted by dst
__device__ int   g_ei_is64;               // dtype flags (auto-detected)
__device__ int   g_b_is64;

// ---------------- dtype detection ------------------------------------------
// int64 payloads with values < 2^31 have all odd 32-bit words zero; int32
// payloads (random edge targets / sorted batch ids in the upper half)
// essentially never do. All sampled offsets are in-bounds under either dtype.
__global__ void detect_k(const int* __restrict__ ei32,
                         const int* __restrict__ b32)
{
    int tid = threadIdx.x;                       // 256 threads, 1 block
    int je = 1 + 12500 * tid;                    // odd words across [1, 2*EE)
    int ei_nz = (ei32[je] != 0);
    int jb = 50001 + 194 * tid;                  // odd words, upper half of N
    int b_nz = (b32[jb] != 0);
    int any_ei = __syncthreads_or(ei_nz);
    int any_b  = __syncthreads_or(b_nz);
    if (tid == 0) {
        g_ei_is64 = (any_ei == 0);
        g_b_is64  = (any_b  == 0);
    }
}

// ---------------- x -> fp16 conversion (layer-1 GEMM input) ----------------
__global__ void cvtx_k(const float* __restrict__ x)
{
    int i = blockIdx.x * blockDim.x + threadIdx.x;   // over N*H/8 uint4
    if (i >= NN * HH / 8) return;
    const float4* p = (const float4*)x + 2 * (size_t)i;
    float4 u0 = p[0], u1 = p[1];
    union { __half2 h[4]; uint4 u; } cv;
    cv.h[0] = __float22half2_rn(make_float2(u0.x, u0.y));
    cv.h[1] = __float22half2_rn(make_float2(u0.z, u0.w));
    cv.h[2] = __float22half2_rn(make_float2(u1.x, u1.y));
    cv.h[3] = __float22half2_rn(make_float2(u1.z, u1.w));
    ((uint4*)g_ah)[i] = cv.u;
}

// ---------------- W -> B-fragment repack (per layer, 4096 threads) ---------
// B fragment for mma.m16n8k16.row.col (B is W[k][n], col-major 16x8 frag):
//   lane: b0=B[t2][g], b1=B[t2+1][g], b2=B[t2+8][g], b3=B[t2+9][g]
//   with t2=(lane%4)*2, g=lane/4;  reg0=(b0,b1), reg1=(b2,b3)
__global__ void repack_k(const float* __restrict__ W)
{
    int tid = blockIdx.x * blockDim.x + threadIdx.x;   // 0..4095
    if (tid >= 16 * 8 * 32) return;
    int lane = tid & 31;
    int kc   = (tid >> 5) & 7;
    int nt   = tid >> 8;
    int k0 = kc * 16 + (lane & 3) * 2;
    int n  = nt * 8 + (lane >> 2);
    float f0 = W[(k0 + 0) * 128 + n];
    float f1 = W[(k0 + 1) * 128 + n];
    float f2 = W[(k0 + 8) * 128 + n];
    float f3 = W[(k0 + 9) * 128 + n];
    union { __half2 h; unsigned u; } lo, hi;
    lo.h = __float22half2_rn(make_float2(f0, f1));
    hi.h = __float22half2_rn(make_float2(f2, f3));
    g_bw[tid] = make_uint2(lo.u, hi.u);
}

// ---------------- init ------------------------------------------------------
__global__ void init_k() {
    int i = blockIdx.x * blockDim.x + threadIdx.x;
    if (i < NN) { g_dinv[i] = 1.0f; g_cnt[i] = 0; g_fill[i] = 0; }
}

// ---------------- edge prep: decode indices, weighted degree, int count ----
__global__ void prep_k(const void* __restrict__ ei,
                       const float* __restrict__ ew) {
    int e = blockIdx.x * blockDim.x + threadIdx.x;
    if (e >= EE) return;
    int r, c;
    if (g_ei_is64) {
        const long long* p = (const long long*)ei;
        r = (int)p[e]; c = (int)p[EE + e];
    } else {
        const int* p = (const int*)ei;
        r = p[e]; c = p[EE + e];
    }
    g_row[e] = r;
    g_col[e] = c;
    atomicAdd(&g_dinv[c], ew[e]);           // weighted in-degree
    atomicAdd(&g_cnt[c], 1);                // integer in-degree (for CSR)
}

__global__ void dinv_k() {
    int i = blockIdx.x * blockDim.x + threadIdx.x;
    if (i >= NN) return;
    float d = g_dinv[i];
    g_dinv[i] = (d > 0.0f) ? rsqrtf(d) : 0.0f;
}

// ---------------- 3-kernel exclusive scan of g_cnt -> g_off ----------------
#define SCAN_B 512
__global__ void scan1_k() {      // per-block exclusive scan + block totals
    __shared__ int sm[SCAN_B];
    int t = threadIdx.x;
    int idx = blockIdx.x * SCAN_B + t;
    int v = (idx < NN) ? g_cnt[idx] : 0;
    sm[t] = v;
    __syncthreads();
#pragma unroll
    for (int o = 1; o < SCAN_B; o <<= 1) {
        int x = (t >= o) ? sm[t - o] : 0;
        __syncthreads();
        sm[t] += x;
        __syncthreads();
    }
    if (idx < NN) g_off[idx] = sm[t] - v;        // exclusive
    if (t == SCAN_B - 1) g_bsum[blockIdx.x] = sm[t];
}
__global__ void scan2_k(int nblk) {  // single block: scan block totals
    __shared__ int sm[256];
    int t = threadIdx.x;
    int v = (t < nblk) ? g_bsum[t] : 0;
    sm[t] = v;
    __syncthreads();
#pragma unroll
    for (int o = 1; o < 256; o <<= 1) {
        int x = (t >= o) ? sm[t - o] : 0;
        __syncthreads();
        sm[t] += x;
        __syncthreads();
    }
    if (t < nblk) g_bsum[t] = sm[t] - v;         // exclusive
}
__global__ void scan3_k() {
    int idx = blockIdx.x * SCAN_B + threadIdx.x;
    if (idx < NN) g_off[idx] += g_bsum[blockIdx.x];
    if (idx == 0) g_off[NN] = EE;
}

// ---------------- build sorted adjacency (counting-sort fill) --------------
__global__ void build_k(const float* __restrict__ ew) {
    int e = blockIdx.x * blockDim.x + threadIdx.x;
    if (e >= EE) return;
    int r = g_row[e], c = g_col[e];
    int pos = g_off[c] + atomicAdd(&g_fill[c], 1);
    g_src[pos] = r;
    g_w[pos]   = g_dinv[r] * ew[e] * g_dinv[c];
}

// ---------------- tensor-core GEMM: g_th = g_ah[N,128] @ W[128,128] --------
// mma.sync.m16n8k16 (fp16 in, fp32 accum). 256 threads = 8 warps per block;
// block tile 128x128, each warp owns a 16-row stripe, all 128 cols.
// A fragments load directly from gmem (reg0/reg2 pair consumes each 32B
// sector fully); B fragments come pre-packed per-lane from g_bw (L1-resident).
__global__ void __launch_bounds__(256)
gemm_tc()
{
    const int lane = threadIdx.x & 31;
    const int warp = threadIdx.x >> 5;
    const int rowbase = blockIdx.x * 128 + warp * 16;

    const int g  = lane >> 2;           // 0..7
    const int t2 = (lane & 3) * 2;      // 0,2,4,6

    // fp32 accumulators: 16 n-tiles x 4
    float c[16][4];
#pragma unroll
    for (int nt = 0; nt < 16; ++nt)
#pragma unroll
        for (int j = 0; j < 4; ++j) c[nt][j] = 0.0f;

    const __half* pA  = g_ah + (size_t)(rowbase + g)     * HH;
    const __half* pA8 = g_ah + (size_t)(rowbase + g + 8) * HH;

#pragma unroll
    for (int kc = 0; kc < 8; ++kc) {
        int off = kc * 16 + t2;
        unsigned a0 = *(const unsigned*)(pA  + off);
        unsigned a1 = *(const unsigned*)(pA8 + off);
        unsigned a2 = *(const unsigned*)(pA  + off + 8);
        unsigned a3 = *(const unsigned*)(pA8 + off + 8);
        const uint2* bb = g_bw + (size_t)kc * 32 + lane;
#pragma unroll
        for (int nt = 0; nt < 16; ++nt) {
            uint2 b = __ldg(bb + (size_t)nt * 8 * 32);
            asm volatile(
                "mma.sync.aligned.m16n8k16.row.col.f32.f16.f16.f32 "
                "{%0,%1,%2,%3}, {%4,%5,%6,%7}, {%8,%9}, {%0,%1,%2,%3};"
                : "+f"(c[nt][0]), "+f"(c[nt][1]),
                  "+f"(c[nt][2]), "+f"(c[nt][3])
                : "r"(a0), "r"(a1), "r"(a2), "r"(a3),
                  "r"(b.x), "r"(b.y));
        }
    }

    // epilogue: fp16 store (c0,c1 -> row rowbase+g; c2,c3 -> row +8)
    const int r0 = rowbase + g;
    const int r1 = r0 + 8;
    const bool ok0 = (r0 < NN);
    const bool ok1 = (r1 < NN);
#pragma unroll
    for (int nt = 0; nt < 16; ++nt) {
        int colb = nt * 8 + t2;
        if (ok0) {
            union { __half2 h; unsigned u; } v;
            v.h = __float22half2_rn(make_float2(c[nt][0], c[nt][1]));
            *(unsigned*)(g_th + (size_t)r0 * HH + colb) = v.u;
        }
        if (ok1) {
            union { __half2 h; unsigned u; } v;
            v.h = __float22half2_rn(make_float2(c[nt][2], c[nt][3]));
            *(unsigned*)(g_th + (size_t)r1 * HH + colb) = v.u;
        }
    }
}

// ---------------- fused aggregation (gather, no atomics) -------------------
// acc = bias + dinv[n]^2 * th[n] + sum_{e in in(n)} w[e] * th[src[e]]  (fp32)
// g_ah[n] = relu(acc) fp16  (next GEMM input / pool input)
// One warp per node; lane l owns channels [4l, 4l+4). 8-edge unroll for MLP.
__global__ void __launch_bounds__(256)
agg_k(const float* __restrict__ bias)
{
    int warp = (blockIdx.x * blockDim.x + threadIdx.x) >> 5;
    if (warp >= NN) return;
    int lane = threadIdx.x & 31;

    float d = g_dinv[warp];
    float s = d * d;
    float4 acc = ((const float4*)bias)[lane];
    {
        uint2 q = *((const uint2*)(g_th + (size_t)warp * HH) + lane);
        float2 f0 = __half22float2(*(const __half2*)&q.x);
        float2 f1 = __half22float2(*(const __half2*)&q.y);
        acc.x = fmaf(f0.x, s, acc.x); acc.y = fmaf(f0.y, s, acc.y);
        acc.z = fmaf(f1.x, s, acc.z); acc.w = fmaf(f1.y, s, acc.w);
    }

    int k   = g_off[warp];
    int end = g_off[warp + 1];

    for (; k + 8 <= end; k += 8) {
        int r[8]; float w[8]; uint2 q[8];
#pragma unroll
        for (int u = 0; u < 8; ++u) { r[u] = g_src[k + u]; w[u] = g_w[k + u]; }
#pragma unroll
        for (int u = 0; u < 8; ++u)
            q[u] = __ldg((const uint2*)(g_th + (size_t)r[u] * HH) + lane);
#pragma unroll
        for (int u = 0; u < 8; ++u) {
            float2 f0 = __half22float2(*(const __half2*)&q[u].x);
            float2 f1 = __half22float2(*(const __half2*)&q[u].y);
            acc.x = fmaf(f0.x, w[u], acc.x);
            acc.y = fmaf(f0.y, w[u], acc.y);
            acc.z = fmaf(f1.x, w[u], acc.z);
            acc.w = fmaf(f1.y, w[u], acc.w);
        }
    }
    for (; k < end; ++k) {
        int   r = g_src[k];
        float w = g_w[k];
        uint2 q = __ldg((const uint2*)(g_th + (size_t)r * HH) + lane);
        float2 f0 = __half22float2(*(const __half2*)&q.x);
        float2 f1 = __half22float2(*(const __half2*)&q.y);
        acc.x = fmaf(f0.x, w, acc.x); acc.y = fmaf(f0.y, w, acc.y);
        acc.z = fmaf(f1.x, w, acc.z); acc.w = fmaf(f1.y, w, acc.w);
    }

    // relu + fp16 store
    acc.x = fmaxf(acc.x, 0.0f); acc.y = fmaxf(acc.y, 0.0f);
    acc.z = fmaxf(acc.z, 0.0f); acc.w = fmaxf(acc.w, 0.0f);
    union { __half2 h[2]; uint2 u; } cv;
    cv.h[0] = __float22half2_rn(make_float2(acc.x, acc.y));
    cv.h[1] = __float22half2_rn(make_float2(acc.z, acc.w));
    *((uint2*)(g_ah + (size_t)warp * HH) + lane) = cv.u;
}

// ---------------- fused pool + final linear (atomic-free) ------------------
// batch is sorted, so graph g occupies a contiguous node range found by
// binary search. One block per graph: thread t owns channel t, sums the
// already-relu'd fp16 activations, then block-reduces the dot with lin_w.
__device__ __forceinline__ int lower_bound_batch(const void* batch, int tgt)
{
    int lo = 0, hi = NN;
    while (lo < hi) {
        int mid = (lo + hi) >> 1;
        long long v = g_b_is64 ? ((const long long*)batch)[mid]
                               : (long long)((const int*)batch)[mid];
        if (v < tgt) lo = mid + 1; else hi = mid;
    }
    return lo;
}

__global__ void poolfinal_k(const void* __restrict__ batch,
                            const float* __restrict__ lw,
                            const float* __restrict__ lb,
                            float* __restrict__ out)
{
    int g = blockIdx.x;       // 64 blocks
    int t = threadIdx.x;      // 128 threads
    __shared__ int se[2];
    if (t == 0) se[0] = lower_bound_batch(batch, g);
    if (t == 1) se[1] = lower_bound_batch(batch, g + 1);
    __syncthreads();
    int s = se[0], e = se[1];

    float sum = 0.0f;
    int r = s;
    for (; r + 4 <= e; r += 4) {
        sum += __half2float(g_ah[(size_t)(r + 0) * HH + t]);
        sum += __half2float(g_ah[(size_t)(r + 1) * HH + t]);
        sum += __half2float(g_ah[(size_t)(r + 2) * HH + t]);
        sum += __half2float(g_ah[(size_t)(r + 3) * HH + t]);
    }
    for (; r < e; ++r)
        sum += __half2float(g_ah[(size_t)r * HH + t]);

    float inv = 1.0f / fmaxf((float)(e - s), 1.0f);
    float v = sum * inv * lw[t];
#pragma unroll
    for (int o = 16; o > 0; o >>= 1)
        v += __shfl_down_sync(0xffffffffu, v, o);
    __shared__ float sm[4];
    if ((t & 31) == 0) sm[t >> 5] = v;
    __syncthreads();
    if (t == 0) out[g] = sm[0] + sm[1] + sm[2] + sm[3] + lb[0];
}

// ---------------- launcher --------------------------------------------------
extern "C" void kernel_launch(void* const* d_in, const int* in_sizes, int n_in,
                              void* d_out, int out_size)
{
    // Locate inputs by element count (robust to metadata ordering).
    const float* x = nullptr;
    const float* ew = nullptr;
    const void*  ei = nullptr;     // int32 or int64 (auto-detected on device)
    const void*  batch = nullptr;  // int32 or int64
    const float* Wm[3] = {nullptr, nullptr, nullptr};
    const float* v128[4] = {nullptr, nullptr, nullptr, nullptr}; // b1,b2,b3,lin_w
    const float* linb = nullptr;
    int wi = 0, bi = 0;
    for (int i = 0; i < n_in; ++i) {
        int s = in_sizes[i];
        if      (s == NN * HH)  x = (const float*)d_in[i];
        else if (s == EE)       ew = (const float*)d_in[i];
        else if (s == 2 * EE)   ei = d_in[i];
        else if (s == NN)       batch = d_in[i];
        else if (s == HH * HH)  { if (wi < 3) Wm[wi++] = (const float*)d_in[i]; }
        else if (s == HH)       { if (bi < 4) v128[bi++] = (const float*)d_in[i]; }
        else if (s == 1)        linb = (const float*)d_in[i];
    }
    const float* lw = v128[3];
    float* out = (float*)d_out;

    const int TB = 256;
    const int gN  = (NN + TB - 1) / TB;
    const int gE  = (EE + TB - 1) / TB;
    const int gCv = (NN * HH / 8 + TB - 1) / TB;
    const int gAg = (int)(((long long)NN * 32 + TB - 1) / TB);  // warp/node
    const int gGm = (NN + 127) / 128;                           // 782
    const int nScanBlk = (NN + SCAN_B - 1) / SCAN_B;            // 196

    // Layer-1 GEMM inputs first (keeps gemm_tc in ncu's capture slot #4),
    // then the CSR preprocessing chain.
    repack_k<<<16, 256>>>(Wm[0]);
    cvtx_k<<<gCv, TB>>>(x);
    detect_k<<<1, 256>>>((const int*)ei, (const int*)batch);
    gemm_tc<<<gGm, TB>>>();                    // th = x @ W1
    init_k<<<gN, TB>>>();
    prep_k<<<gE, TB>>>(ei, ew);
    dinv_k<<<gN, TB>>>();
    scan1_k<<<nScanBlk, SCAN_B>>>();
    scan2_k<<<1, 256>>>(nScanBlk);
    scan3_k<<<nScanBlk, SCAN_B>>>();
    build_k<<<gE, TB>>>(ew);

    // Layer 1 aggregation: ah = relu(b1 + dinv^2*th + gather(th))
    agg_k<<<gAg, TB>>>(v128[0]);

    // Layer 2
    repack_k<<<16, 256>>>(Wm[1]);
    gemm_tc<<<gGm, TB>>>();
    agg_k<<<gAg, TB>>>(v128[1]);

    // Layer 3
    repack_k<<<16, 256>>>(Wm[2]);
    gemm_tc<<<gGm, TB>>>();
    agg_k<<<gAg, TB>>>(v128[2]);

    // Fused pool + final linear
    poolfinal_k<<<GG, 128>>>(batch, lw, linb, out);
}

// round 12
// speedup vs baseline: 6.8431x; 1.4235x over previous
#include <cuda_runtime.h>
#include <cuda_fp16.h>
#include <math.h>

// Problem constants (fixed by the reference)
#define NN 100000   // nodes
#define EE 1600000  // edges
#define HH 128      // channels
#define GG 64       // graphs
#define PCH 8       // pool chunks per graph

// ---------------- static device scratch (no allocations allowed) ----------
// fp16 activation ping-pong (fp32 math, fp16 storage):
//   g_ah : GEMM input for layers 2/3 (relu'd activations), padded 128 rows
//   g_th : GEMM output (transformed features; agg gathers from here), padded
__device__ __align__(16) __half g_ah[(size_t)(NN + 128) * HH];
__device__ __align__(16) __half g_th[(size_t)(NN + 128) * HH];
__device__ __align__(16) uint2  g_bw[16 * 8 * 32];   // repacked W B-fragments
__device__ float g_dinv[NN];              // deg -> d^{-1/2} (in place)
__device__ int   g_row[EE];
__device__ int   g_col[EE];
// CSR (destination-sorted) adjacency, built once
__device__ int   g_cnt[NN];               // int in-degree
__device__ int   g_off[NN + 1];           // exclusive scan of cnt
__device__ int   g_fill[NN];              // slot fill counters
__device__ int   g_bsum[256];             // block sums for scan
__device__ __align__(8) int2 g_adj[EE];   // {src, w-bits}, sorted by dst
__device__ float g_part[GG * PCH];        // pool partial dots
__device__ int   g_ei_is64;               // dtype flags (auto-detected)
__device__ int   g_b_is64;

// ---------------- init + dtype detection (fused) ----------------------------
// int64 payloads with values < 2^31 have all odd 32-bit words zero; int32
// payloads (random edge targets / sorted batch ids in the upper half)
// essentially never do. All sampled offsets are in-bounds under either dtype.
__global__ void init_k(const int* __restrict__ ei32,
                       const int* __restrict__ b32)
{
    int i = blockIdx.x * blockDim.x + threadIdx.x;
    if (i < NN) { g_dinv[i] = 1.0f; g_cnt[i] = 0; g_fill[i] = 0; }
    if (blockIdx.x == 0) {
        int tid = threadIdx.x;                   // 256 threads
        int je = 1 + 12500 * tid;                // odd words across [1, 2*EE)
        int ei_nz = (ei32[je] != 0);
        int jb = 50001 + 194 * tid;              // odd words, upper half of N
        int b_nz = (b32[jb] != 0);
        int any_ei = __syncthreads_or(ei_nz);
        int any_b  = __syncthreads_or(b_nz);
        if (tid == 0) {
            g_ei_is64 = (any_ei == 0);
            g_b_is64  = (any_b  == 0);
        }
    }
}

// ---------------- W -> B-fragment repack (per layer, 4096 threads) ---------
// B fragment for mma.m16n8k16.row.col (B is W[k][n], col-major 16x8 frag):
//   lane: b0=B[t2][g], b1=B[t2+1][g], b2=B[t2+8][g], b3=B[t2+9][g]
//   with t2=(lane%4)*2, g=lane/4;  reg0=(b0,b1), reg1=(b2,b3)
// Layout: g_bw[nt*256 + kc*32 + lane]
__global__ void repack_k(const float* __restrict__ W)
{
    int tid = blockIdx.x * blockDim.x + threadIdx.x;   // 0..4095
    if (tid >= 16 * 8 * 32) return;
    int lane = tid & 31;
    int kc   = (tid >> 5) & 7;
    int nt   = tid >> 8;
    int k0 = kc * 16 + (lane & 3) * 2;
    int n  = nt * 8 + (lane >> 2);
    float f0 = W[(k0 + 0) * 128 + n];
    float f1 = W[(k0 + 1) * 128 + n];
    float f2 = W[(k0 + 8) * 128 + n];
    float f3 = W[(k0 + 9) * 128 + n];
    union { __half2 h; unsigned u; } lo, hi;
    lo.h = __float22half2_rn(make_float2(f0, f1));
    hi.h = __float22half2_rn(make_float2(f2, f3));
    g_bw[tid] = make_uint2(lo.u, hi.u);
}

// ---------------- edge prep: decode indices, weighted degree, int count ----
__global__ void prep_k(const void* __restrict__ ei,
                       const float* __restrict__ ew) {
    int e = blockIdx.x * blockDim.x + threadIdx.x;
    if (e >= EE) return;
    int r, c;
    if (g_ei_is64) {
        const long long* p = (const long long*)ei;
        r = (int)p[e]; c = (int)p[EE + e];
    } else {
        const int* p = (const int*)ei;
        r = p[e]; c = p[EE + e];
    }
    g_row[e] = r;
    g_col[e] = c;
    atomicAdd(&g_dinv[c], ew[e]);           // weighted in-degree
    atomicAdd(&g_cnt[c], 1);                // integer in-degree (for CSR)
}

// ---------------- exclusive scan of g_cnt -> g_off (+ fused dinv) ----------
#define SCAN_B 512
__global__ void scan1_k() {      // per-block exclusive scan + block totals
    __shared__ int sm[SCAN_B];
    int t = threadIdx.x;
    int idx = blockIdx.x * SCAN_B + t;
    int v = (idx < NN) ? g_cnt[idx] : 0;
    sm[t] = v;
    // fused: deg -> d^{-1/2}
    if (idx < NN) {
        float d = g_dinv[idx];
        g_dinv[idx] = (d > 0.0f) ? rsqrtf(d) : 0.0f;
    }
    __syncthreads();
#pragma unroll
    for (int o = 1; o < SCAN_B; o <<= 1) {
        int x = (t >= o) ? sm[t - o] : 0;
        __syncthreads();
        sm[t] += x;
        __syncthreads();
    }
    if (idx < NN) g_off[idx] = sm[t] - v;        // exclusive
    if (t == SCAN_B - 1) g_bsum[blockIdx.x] = sm[t];
}
__global__ void scan2_k(int nblk) {  // single block: scan block totals
    __shared__ int sm[256];
    int t = threadIdx.x;
    int v = (t < nblk) ? g_bsum[t] : 0;
    sm[t] = v;
    __syncthreads();
#pragma unroll
    for (int o = 1; o < 256; o <<= 1) {
        int x = (t >= o) ? sm[t - o] : 0;
        __syncthreads();
        sm[t] += x;
        __syncthreads();
    }
    if (t < nblk) g_bsum[t] = sm[t] - v;         // exclusive
}
__global__ void scan3_k() {
    int idx = blockIdx.x * SCAN_B + threadIdx.x;
    if (idx < NN) g_off[idx] += g_bsum[blockIdx.x];
    if (idx == 0) g_off[NN] = EE;
}

// ---------------- build sorted adjacency (counting-sort fill) --------------
__global__ void build_k(const float* __restrict__ ew) {
    int e = blockIdx.x * blockDim.x + threadIdx.x;
    if (e >= EE) return;
    int r = g_row[e], c = g_col[e];
    int pos = g_off[c] + atomicAdd(&g_fill[c], 1);
    float w = g_dinv[r] * ew[e] * g_dinv[c];
    g_adj[pos] = make_int2(r, __float_as_int(w));
}

// ---------------- tensor-core GEMM: g_th = A[N,128] @ W[128,128] -----------
// mma.sync.m16n8k16 (fp16 in, fp32 accum). 256 threads = 8 warps per block;
// block tile 64x128: warp tile m16 x n64 (32 accum regs -> 3 CTAs/SM).
// F32IN: layer-1 path loads fp32 x directly and converts in-register.
template<bool F32IN>
__global__ void __launch_bounds__(256, 3)
gemm_tc(const float* __restrict__ xA)
{
    const int lane = threadIdx.x & 31;
    const int warp = threadIdx.x >> 5;                 // 0..7
    const int rowbase = blockIdx.x * 64 + (warp & 3) * 16;
    const int ntbase  = (warp >> 2) * 8;               // 0 or 8

    const int g  = lane >> 2;           // 0..7
    const int t2 = (lane & 3) * 2;      // 0,2,4,6

    float c[8][4];
#pragma unroll
    for (int nt = 0; nt < 8; ++nt)
#pragma unroll
        for (int j = 0; j < 4; ++j) c[nt][j] = 0.0f;

    const int r0 = rowbase + g;
    const int r1 = r0 + 8;
    const bool ok0 = (r0 < NN);
    const bool ok1 = (r1 < NN);

    const __half* pH0 = g_ah + (size_t)r0 * HH;
    const __half* pH1 = g_ah + (size_t)r1 * HH;
    const float*  pF0 = xA + (size_t)r0 * HH;
    const float*  pF1 = xA + (size_t)r1 * HH;

#pragma unroll
    for (int kc = 0; kc < 8; ++kc) {
        int off = kc * 16 + t2;
        unsigned a0, a1, a2, a3;
        if (F32IN) {
            float2 f0 = ok0 ? *(const float2*)(pF0 + off)
                            : make_float2(0.f, 0.f);
            float2 f1 = ok1 ? *(const float2*)(pF1 + off)
                            : make_float2(0.f, 0.f);
            float2 f2 = ok0 ? *(const float2*)(pF0 + off + 8)
                            : make_float2(0.f, 0.f);
            float2 f3 = ok1 ? *(const float2*)(pF1 + off + 8)
                            : make_float2(0.f, 0.f);
            union { __half2 h; unsigned u; } u0, u1, u2, u3;
            u0.h = __float22half2_rn(f0); u1.h = __float22half2_rn(f1);
            u2.h = __float22half2_rn(f2); u3.h = __float22half2_rn(f3);
            a0 = u0.u; a1 = u1.u; a2 = u2.u; a3 = u3.u;
        } else {
            a0 = *(const unsigned*)(pH0 + off);
            a1 = *(const unsigned*)(pH1 + off);
            a2 = *(const unsigned*)(pH0 + off + 8);
            a3 = *(const unsigned*)(pH1 + off + 8);
        }
        const uint2* bb = g_bw + (size_t)kc * 32 + lane;
#pragma unroll
        for (int nt = 0; nt < 8; ++nt) {
            uint2 b = __ldg(bb + (size_t)(ntbase + nt) * 256);
            asm volatile(
                "mma.sync.aligned.m16n8k16.row.col.f32.f16.f16.f32 "
                "{%0,%1,%2,%3}, {%4,%5,%6,%7}, {%8,%9}, {%0,%1,%2,%3};"
                : "+f"(c[nt][0]), "+f"(c[nt][1]),
                  "+f"(c[nt][2]), "+f"(c[nt][3])
                : "r"(a0), "r"(a1), "r"(a2), "r"(a3),
                  "r"(b.x), "r"(b.y));
        }
    }

    // epilogue: fp16 store (c0,c1 -> row r0; c2,c3 -> row r1)
#pragma unroll
    for (int nt = 0; nt < 8; ++nt) {
        int colb = (ntbase + nt) * 8 + t2;
        if (ok0) {
            union { __half2 h; unsigned u; } v;
            v.h = __float22half2_rn(make_float2(c[nt][0], c[nt][1]));
            *(unsigned*)(g_th + (size_t)r0 * HH + colb) = v.u;
        }
        if (ok1) {
            union { __half2 h; unsigned u; } v;
            v.h = __float22half2_rn(make_float2(c[nt][2], c[nt][3]));
            *(unsigned*)(g_th + (size_t)r1 * HH + colb) = v.u;
        }
    }
}

// ---------------- fused aggregation (gather, no atomics) -------------------
// acc = bias + dinv[n]^2 * th[n] + sum_{e in in(n)} w[e] * th[src[e]]  (fp32)
// g_ah[n] = relu(acc) fp16  (next GEMM input / pool input)
// One warp per node; lane l owns channels [4l, 4l+4). 16-edge unroll.
__global__ void __launch_bounds__(256)
agg_k(const float* __restrict__ bias)
{
    int warp = (blockIdx.x * blockDim.x + threadIdx.x) >> 5;
    if (warp >= NN) return;
    int lane = threadIdx.x & 31;

    float d = g_dinv[warp];
    float s = d * d;
    float4 acc = ((const float4*)bias)[lane];
    {
        uint2 q = *((const uint2*)(g_th + (size_t)warp * HH) + lane);
        float2 f0 = __half22float2(*(const __half2*)&q.x);
        float2 f1 = __half22float2(*(const __half2*)&q.y);
        acc.x = fmaf(f0.x, s, acc.x); acc.y = fmaf(f0.y, s, acc.y);
        acc.z = fmaf(f1.x, s, acc.z); acc.w = fmaf(f1.y, s, acc.w);
    }

    int k   = g_off[warp];
    int end = g_off[warp + 1];

    for (; k + 16 <= end; k += 16) {
        int2 a[16]; uint2 q[16];
#pragma unroll
        for (int u = 0; u < 16; ++u) a[u] = __ldg(&g_adj[k + u]);
#pragma unroll
        for (int u = 0; u < 16; ++u)
            q[u] = __ldg((const uint2*)(g_th + (size_t)a[u].x * HH) + lane);
#pragma unroll
        for (int u = 0; u < 16; ++u) {
            float w = __int_as_float(a[u].y);
            float2 f0 = __half22float2(*(const __half2*)&q[u].x);
            float2 f1 = __half22float2(*(const __half2*)&q[u].y);
            acc.x = fmaf(f0.x, w, acc.x);
            acc.y = fmaf(f0.y, w, acc.y);
            acc.z = fmaf(f1.x, w, acc.z);
            acc.w = fmaf(f1.y, w, acc.w);
        }
    }
    for (; k + 4 <= end; k += 4) {
        int2 a[4]; uint2 q[4];
#pragma unroll
        for (int u = 0; u < 4; ++u) a[u] = __ldg(&g_adj[k + u]);
#pragma unroll
        for (int u = 0; u < 4; ++u)
            q[u] = __ldg((const uint2*)(g_th + (size_t)a[u].x * HH) + lane);
#pragma unroll
        for (int u = 0; u < 4; ++u) {
            float w = __int_as_float(a[u].y);
            float2 f0 = __half22float2(*(const __half2*)&q[u].x);
            float2 f1 = __half22float2(*(const __half2*)&q[u].y);
            acc.x = fmaf(f0.x, w, acc.x);
            acc.y = fmaf(f0.y, w, acc.y);
            acc.z = fmaf(f1.x, w, acc.z);
            acc.w = fmaf(f1.y, w, acc.w);
        }
    }
    for (; k < end; ++k) {
        int2 a = __ldg(&g_adj[k]);
        float w = __int_as_float(a.y);
        uint2 q = __ldg((const uint2*)(g_th + (size_t)a.x * HH) + lane);
        float2 f0 = __half22float2(*(const __half2*)&q.x);
        float2 f1 = __half22float2(*(const __half2*)&q.y);
        acc.x = fmaf(f0.x, w, acc.x); acc.y = fmaf(f0.y, w, acc.y);
        acc.z = fmaf(f1.x, w, acc.z); acc.w = fmaf(f1.y, w, acc.w);
    }

    // relu + fp16 store
    acc.x = fmaxf(acc.x, 0.0f); acc.y = fmaxf(acc.y, 0.0f);
    acc.z = fmaxf(acc.z, 0.0f); acc.w = fmaxf(acc.w, 0.0f);
    union { __half2 h[2]; uint2 u; } cv;
    cv.h[0] = __float22half2_rn(make_float2(acc.x, acc.y));
    cv.h[1] = __float22half2_rn(make_float2(acc.z, acc.w));
    *((uint2*)(g_ah + (size_t)warp * HH) + lane) = cv.u;
}

// ---------------- two-stage pool + final linear (atomic-free) --------------
__device__ __forceinline__ int lower_bound_batch(const void* batch, int tgt)
{
    int lo = 0, hi = NN;
    while (lo < hi) {
        int mid = (lo + hi) >> 1;
        long long v = g_b_is64 ? ((const long long*)batch)[mid]
                               : (long long)((const int*)batch)[mid];
        if (v < tgt) lo = mid + 1; else hi = mid;
    }
    return lo;
}

// stage 1: 512 blocks = 64 graphs x 8 chunks; partial dot of channel sums
// with lin_w over a row sub-range (linear, so chunk partials sum exactly).
__global__ void pool1_k(const void* __restrict__ batch,
                        const float* __restrict__ lw)
{
    int g  = blockIdx.x >> 3;        // graph
    int ch = blockIdx.x & 7;         // chunk
    int t  = threadIdx.x;            // 128 threads = channel
    __shared__ int se[2];
    if (t == 0) se[0] = lower_bound_batch(batch, g);
    if (t == 1) se[1] = lower_bound_batch(batch, g + 1);
    __syncthreads();
    int s = se[0], len = se[1] - se[0];
    int c0 = s + (int)(((long long)len * ch) >> 3);
    int c1 = s + (int)(((long long)len * (ch + 1)) >> 3);

    float sum = 0.0f;
    int r = c0;
    for (; r + 4 <= c1; r += 4) {
        sum += __half2float(g_ah[(size_t)(r + 0) * HH + t]);
        sum += __half2float(g_ah[(size_t)(r + 1) * HH + t]);
        sum += __half2float(g_ah[(size_t)(r + 2) * HH + t]);
        sum += __half2float(g_ah[(size_t)(r + 3) * HH + t]);
    }
    for (; r < c1; ++r)
        sum += __half2float(g_ah[(size_t)r * HH + t]);

    float v = sum * lw[t];
#pragma unroll
    for (int o = 16; o > 0; o >>= 1)
        v += __shfl_down_sync(0xffffffffu, v, o);
    __shared__ float sm[4];
    if ((t & 31) == 0) sm[t >> 5] = v;
    __syncthreads();
    if (t == 0) g_part[blockIdx.x] = sm[0] + sm[1] + sm[2] + sm[3];
}

// stage 2: combine chunk partials, divide by node count, add bias.
__global__ void final_k(const void* __restrict__ batch,
                        const float* __restrict__ lb,
                        float* __restrict__ out)
{
    int g = threadIdx.x;             // 64 threads
    if (g >= GG) return;
    int s = lower_bound_batch(batch, g);
    int e = lower_bound_batch(batch, g + 1);
    float sum = 0.0f;
#pragma unroll
    for (int c = 0; c < PCH; ++c) sum += g_part[g * PCH + c];
    out[g] = sum / fmaxf((float)(e - s), 1.0f) + lb[0];
}

// ---------------- launcher --------------------------------------------------
extern "C" void kernel_launch(void* const* d_in, const int* in_sizes, int n_in,
                              void* d_out, int out_size)
{
    // Locate inputs by element count (robust to metadata ordering).
    const float* x = nullptr;
    const float* ew = nullptr;
    const void*  ei = nullptr;     // int32 or int64 (auto-detected on device)
    const void*  batch = nullptr;  // int32 or int64
    const float* Wm[3] = {nullptr, nullptr, nullptr};
    const float* v128[4] = {nullptr, nullptr, nullptr, nullptr}; // b1,b2,b3,lin_w
    const float* linb = nullptr;
    int wi = 0, bi = 0;
    for (int i = 0; i < n_in; ++i) {
        int s = in_sizes[i];
        if      (s == NN * HH)  x = (const float*)d_in[i];
        else if (s == EE)       ew = (const float*)d_in[i];
        else if (s == 2 * EE)   ei = d_in[i];
        else if (s == NN)       batch = d_in[i];
        else if (s == HH * HH)  { if (wi < 3) Wm[wi++] = (const float*)d_in[i]; }
        else if (s == HH)       { if (bi < 4) v128[bi++] = (const float*)d_in[i]; }
        else if (s == 1)        linb = (const float*)d_in[i];
    }
    const float* lw = v128[3];
    float* out = (float*)d_out;

    const int TB = 256;
    const int gN  = (NN + TB - 1) / TB;
    const int gE  = (EE + TB - 1) / TB;
    const int gAg = (int)(((long long)NN * 32 + TB - 1) / TB);  // warp/node
    const int gGm = (NN + 63) / 64;                             // 1563
    const int nScanBlk = (NN + SCAN_B - 1) / SCAN_B;            // 196

    // Order keeps layer-1 GEMM at launch slot 4 (ncu capture window).
    repack_k<<<16, 256>>>(Wm[0]);
    init_k<<<gN, TB>>>((const int*)ei, (const int*)batch);
    prep_k<<<gE, TB>>>(ei, ew);
    gemm_tc<true><<<gGm, TB>>>(x);             // th = x @ W1 (fp32 input)
    scan1_k<<<nScanBlk, SCAN_B>>>();           // scan + dinv
    scan2_k<<<1, 256>>>(nScanBlk);
    scan3_k<<<nScanBlk, SCAN_B>>>();
    build_k<<<gE, TB>>>(ew);

    // Layer 1 aggregation: ah = relu(b1 + dinv^2*th + gather(th))
    agg_k<<<gAg, TB>>>(v128[0]);

    // Layer 2
    repack_k<<<16, 256>>>(Wm[1]);
    gemm_tc<false><<<gGm, TB>>>(x);
    agg_k<<<gAg, TB>>>(v128[1]);

    // Layer 3
    repack_k<<<16, 256>>>(Wm[2]);
    gemm_tc<false><<<gGm, TB>>>(x);
    agg_k<<<gAg, TB>>>(v128[2]);

    // Two-stage pool + final linear
    pool1_k<<<GG * PCH, 128>>>(batch, lw);
    final_k<<<1, 64>>>(batch, linb, out);
}